// round 10
// baseline (speedup 1.0000x reference)
#include <cuda_runtime.h>
#include <cuda_bf16.h>
#include <stdint.h>
#include <math.h>

#define BLK 256
#define NAG 32
#define NA  4096
#define DD  256
#define NE  31

#define OFF_LOG 2097152L
#define OFF_UNN 2224128L
#define OFF_ENT 2351104L
#define OFF_HW  2351105L
#define OFF_CMB 2478081L

typedef __nv_bfloat16 bf16;

// ------- scratch: bf16 (hi, mid) planes for all GEMM operands -------
__device__ bf16 g_H1h[NA * 128], g_H1m[NA * 128];
__device__ bf16 g_FINh[NA * 512], g_FINm[NA * 512];   // [AE | X]
__device__ bf16 g_Weh[256 * 128], g_Wem[256 * 128];
__device__ bf16 g_Whh[256 * 256], g_Whm[256 * 256];
__device__ bf16 g_Wdh[512 * 512], g_Wdm[512 * 512];
__device__ float g_AE[NA * DD];
__device__ float g_BASE[NA * DD];
__device__ float g_ENT[NA];
__device__ float g_W2e[2 * DD];
__device__ float g_b2e[2];
__device__ float g_QKW[DD * 10];
__device__ float g_pW2e[8 * 512];
__device__ float g_pQKW[8 * DD * 10];
__device__ float g_pb2e[16];

// ------- bf16 2-way split -------
__device__ __forceinline__ void split2(float x, bf16& h, bf16& m) {
    h = __float2bfloat16_rn(x);
    m = __float2bfloat16_rn(x - __bfloat162float(h));
}

// ------- bf16 m16n8k16 MMA (legacy HMMA; supported on plain sm_103) -------
__device__ __forceinline__ void mma_bf16(float* d, const uint32_t* a,
                                         uint32_t b0, uint32_t b1) {
    asm volatile(
        "mma.sync.aligned.m16n8k16.row.col.f32.bf16.bf16.f32 "
        "{%0,%1,%2,%3}, {%4,%5,%6,%7}, {%8,%9}, {%0,%1,%2,%3};\n"
        : "+f"(d[0]), "+f"(d[1]), "+f"(d[2]), "+f"(d[3])
        : "r"(a[0]), "r"(a[1]), "r"(a[2]), "r"(a[3]), "r"(b0), "r"(b1));
}

// ------- bf16-split tensor GEMM: C = act(A[MxK] @ W[NxK]^T + bias) ------
// BM=BN=64, BK=16, 256 threads = 8 warps in 4(m) x 2(n); warp tile 16x32.
// Operands pre-split into (h,m) bf16 planes; 3 passes: hh + mh + hm.
// Requires M%64==0, N%64==0, K%16==0, lda%4==0, ldw%4==0.
template <int ACT, int PACK>
__global__ void __launch_bounds__(256)
gemm_bf(const bf16* __restrict__ Ah, const bf16* __restrict__ Am, int lda,
        const bf16* __restrict__ Wh, const bf16* __restrict__ Wm, int ldw,
        const float* __restrict__ bias, float* __restrict__ C, int ldc,
        bf16* __restrict__ Cph, bf16* __restrict__ Cpm, int ldcp, int K)
{
    // rows of 8 bf16x2 units + 1 pad word
    __shared__ uint32_t Ash[64][9], Asm_[64][9], Bsh[64][9], Bsm_[64][9];
    int tid = threadIdx.x;
    int lane = tid & 31, wid = tid >> 5;
    int g = lane >> 2, tig = lane & 3;
    int wm = wid >> 1, wn = wid & 1;
    int bm = blockIdx.y * 64, bn = blockIdx.x * 64;

    float acc[4][4];
#pragma unroll
    for (int nt = 0; nt < 4; nt++)
#pragma unroll
        for (int q = 0; q < 4; q++) acc[nt][q] = 0.f;

    int pr = tid & 63, pu = tid >> 6;   // staging: row, unit-pair (0..3)
    const bf16* ArH = Ah + (size_t)(bm + pr) * lda + pu * 4;
    const bf16* ArM = Am + (size_t)(bm + pr) * lda + pu * 4;
    const bf16* WrH = Wh + (size_t)(bn + pr) * ldw + pu * 4;
    const bf16* WrM = Wm + (size_t)(bn + pr) * ldw + pu * 4;

    for (int k0 = 0; k0 < K; k0 += 16) {
        uint2 va = *(const uint2*)(ArH + k0);
        uint2 vm = *(const uint2*)(ArM + k0);
        uint2 wa = *(const uint2*)(WrH + k0);
        uint2 wmv = *(const uint2*)(WrM + k0);
        Ash[pr][pu * 2] = va.x;  Ash[pr][pu * 2 + 1] = va.y;
        Asm_[pr][pu * 2] = vm.x; Asm_[pr][pu * 2 + 1] = vm.y;
        Bsh[pr][pu * 2] = wa.x;  Bsh[pr][pu * 2 + 1] = wa.y;
        Bsm_[pr][pu * 2] = wmv.x; Bsm_[pr][pu * 2 + 1] = wmv.y;
        __syncthreads();

        int ar = wm * 16 + g;
        uint32_t ah[4] = {Ash[ar][tig], Ash[ar + 8][tig],
                          Ash[ar][tig + 4], Ash[ar + 8][tig + 4]};
        uint32_t am[4] = {Asm_[ar][tig], Asm_[ar + 8][tig],
                          Asm_[ar][tig + 4], Asm_[ar + 8][tig + 4]};
#pragma unroll
        for (int nt = 0; nt < 4; nt++) {
            int br = wn * 32 + nt * 8 + g;
            uint32_t bh0 = Bsh[br][tig], bh1 = Bsh[br][tig + 4];
            uint32_t bm0 = Bsm_[br][tig], bm1 = Bsm_[br][tig + 4];
            mma_bf16(acc[nt], ah, bh0, bh1);   // hi*hi
            mma_bf16(acc[nt], am, bh0, bh1);   // mid*hi
            mma_bf16(acc[nt], ah, bm0, bm1);   // hi*mid
        }
        __syncthreads();
    }

    // epilogue: c0:(g,2t) c1:(g,2t+1) c2:(g+8,2t) c3:(g+8,2t+1)
    long gm0 = bm + wm * 16 + g;
    long gm1 = gm0 + 8;
#pragma unroll
    for (int nt = 0; nt < 4; nt++) {
        long gn = bn + wn * 32 + nt * 8 + 2 * tig;
        float b0 = bias[gn], b1 = bias[gn + 1];
        float v00 = acc[nt][0] + b0, v01 = acc[nt][1] + b1;
        float v10 = acc[nt][2] + b0, v11 = acc[nt][3] + b1;
        if (ACT == 1) {
            v00 = fmaxf(v00, 0.f); v01 = fmaxf(v01, 0.f);
            v10 = fmaxf(v10, 0.f); v11 = fmaxf(v11, 0.f);
        }
        if (ACT == 2) {
            v00 = v00 > 0.f ? v00 : 0.01f * v00;
            v01 = v01 > 0.f ? v01 : 0.01f * v01;
            v10 = v10 > 0.f ? v10 : 0.01f * v10;
            v11 = v11 > 0.f ? v11 : 0.01f * v11;
        }
        *(float2*)&C[gm0 * ldc + gn] = make_float2(v00, v01);
        *(float2*)&C[gm1 * ldc + gn] = make_float2(v10, v11);
        if (PACK) {
            bf16 h, m;
            split2(v00, h, m); Cph[gm0 * ldcp + gn] = h;     Cpm[gm0 * ldcp + gn] = m;
            split2(v01, h, m); Cph[gm0 * ldcp + gn + 1] = h; Cpm[gm0 * ldcp + gn + 1] = m;
            split2(v10, h, m); Cph[gm1 * ldcp + gn] = h;     Cpm[gm1 * ldcp + gn] = m;
            split2(v11, h, m); Cph[gm1 * ldcp + gn + 1] = h; Cpm[gm1 * ldcp + gn + 1] = m;
        }
    }
}

// ------- weight pre-pack (2-way bf16 split) -------
__global__ void packW_kernel(const float* __restrict__ emb2w,
                             const float* __restrict__ hm1w,
                             const float* __restrict__ decw)
{
    int i = blockIdx.x * 256 + threadIdx.x;
    bf16 h, m;
    if (i < 32768) {
        split2(emb2w[i], h, m);
        g_Weh[i] = h; g_Wem[i] = m;
    } else if (i < 98304) {
        int j = i - 32768;
        split2(hm1w[(j >> 8) * 263 + (j & 255)], h, m);
        g_Whh[j] = h; g_Whm[j] = m;
    } else if (i < 360448) {
        int j = i - 98304;
        split2(decw[j], h, m);
        g_Wdh[j] = h; g_Wdm[j] = m;
    }
}

// ------- fold stage A -------
__global__ void foldA_kernel(const float* __restrict__ he_w,
                             const float* __restrict__ hm2_w, const float* __restrict__ hm2_b,
                             const float* __restrict__ q_w, const float* __restrict__ k_w)
{
    int p = blockIdx.x;
    int t = threadIdx.x;
    float s0 = 0.f, s1 = 0.f;
#pragma unroll 8
    for (int m = 0; m < 32; m++) {
        int mm = p * 32 + m;
        float w2 = hm2_w[mm * DD + t];
        s0 += he_w[mm] * w2;
        s1 += he_w[DD + mm] * w2;
    }
    g_pW2e[p * 512 + t] = s0;
    g_pW2e[p * 512 + 256 + t] = s1;

    float acc[10];
#pragma unroll
    for (int f = 0; f < 10; f++) acc[f] = 0.f;
#pragma unroll 4
    for (int d = 0; d < 32; d++) {
        int dd = p * 32 + d;
        float qv = q_w[dd * DD + t];
#pragma unroll
        for (int f = 0; f < 10; f++) acc[f] += qv * k_w[dd * 10 + f];
    }
#pragma unroll
    for (int f = 0; f < 10; f++) g_pQKW[(p * DD + t) * 10 + f] = acc[f];

    if (t < 2) {
        float s = 0.f;
        for (int m = 0; m < 32; m++) {
            int mm = p * 32 + m;
            s += he_w[t * DD + mm] * hm2_b[mm];
        }
        g_pb2e[p * 2 + t] = s;
    }
}

// ------- fold stage B: wide combine -------
__global__ void foldB_kernel(const float* __restrict__ he_b)
{
    int idx = blockIdx.x * 256 + threadIdx.x;
    if (idx < 512) {
        float s = 0.f;
#pragma unroll
        for (int p = 0; p < 8; p++) s += g_pW2e[p * 512 + idx];
        g_W2e[idx] = s;
    } else if (idx < 3072) {
        int j = idx - 512;
        float s = 0.f;
#pragma unroll
        for (int p = 0; p < 8; p++) s += g_pQKW[p * 2560 + j];
        g_QKW[j] = s;
    } else if (idx < 3074) {
        int t = idx - 3072;
        float s = he_b[t];
#pragma unroll
        for (int p = 0; p < 8; p++) s += g_pb2e[p * 2 + t];
        g_b2e[t] = s;
    }
}

// ------- H1 = leaky(emb[:,4:9] @ emb1_w^T + b), split output -------
__global__ void h1_kernel(const float* __restrict__ emb,
                          const float* __restrict__ w, const float* __restrict__ b)
{
    __shared__ float sw[128 * 5];
    __shared__ float sb2[128];
    int tid = threadIdx.x;
    for (int e = tid; e < 640; e += 256) sw[e] = w[e];
    if (tid < 128) sb2[tid] = b[tid];
    __syncthreads();
    int r = blockIdx.x * 2 + (tid >> 7);
    int c = tid & 127;
    const float* er = emb + (long)r * 11 + 4;
    float e0 = er[0], e1 = er[1], e2 = er[2], e3 = er[3], e4 = er[4];
    const float* wc = &sw[c * 5];
    float v = sb2[c] + e0 * wc[0] + e1 * wc[1] + e2 * wc[2] + e3 * wc[3] + e4 * wc[4];
    v = v > 0.f ? v : 0.01f * v;
    bf16 h, m;
    split2(v, h, m);
    long idx = (long)r * 128 + c;
    g_H1h[idx] = h; g_H1m[idx] = m;
}

// ------- fused per-agent edge kernel -------
#define SEP 12
__global__ void edge_kernel(const float* __restrict__ emb,
                            const float* __restrict__ gum,
                            const float* __restrict__ hm1_w,
                            const float* __restrict__ v_w,
                            const float* __restrict__ v_b,
                            float* __restrict__ out)
{
    int a = blockIdx.x;
    int bb = a >> 5, i = a & 31;
    int tid = threadIdx.x;
    int lane = tid & 31, warp = tid >> 5;

    __shared__ float s_emb[NAG * 11];
    __shared__ float s_WE[DD * 7];
    __shared__ float s_W2[2 * DD];
    __shared__ float s_b2[2];
    __shared__ float s_VW[DD * 10];
    __shared__ float s_vb[DD];
    __shared__ float s_base[DD];
    __shared__ float s_qk[10];
    __shared__ __align__(16) float s_se[NAG][SEP];
    __shared__ float s_sc[NAG];
    __shared__ float s_hw[NAG];
    __shared__ float s_cb[NAG];
    __shared__ float s_red[8 * 10];

    for (int e = tid; e < NAG * 11; e += BLK) s_emb[e] = emb[bb * NAG * 11 + e];
    for (int e = tid; e < DD * 7; e += BLK) s_WE[e] = hm1_w[(e / 7) * 263 + 256 + (e % 7)];
    s_W2[tid] = g_W2e[tid];
    s_W2[DD + tid] = g_W2e[DD + tid];
    for (int e = tid; e < DD * 10; e += BLK) s_VW[e] = v_w[e];
    s_vb[tid] = v_b[tid];
    s_base[tid] = g_BASE[(long)a * DD + tid];
    if (tid < 2) s_b2[tid] = g_b2e[tid];

    float av = g_AE[(long)a * DD + tid];
#pragma unroll
    for (int f = 0; f < 10; f++) {
        float p = av * g_QKW[tid * 10 + f];
        for (int o = 16; o; o >>= 1) p += __shfl_down_sync(0xffffffffu, p, o);
        if (lane == 0) s_red[warp * 10 + f] = p;
    }
    __syncthreads();
    if (tid < 10) {
        float s = 0.f;
        for (int w = 0; w < 8; w++) s += s_red[w * 10 + tid];
        s_qk[tid] = s;
    }
    __syncthreads();

    if (tid < NAG) {
        int j = tid;
        s_se[j][10] = 0.f; s_se[j][11] = 0.f;
        if (j == i) {
            s_sc[j] = -1e30f; s_hw[j] = 0.f; s_cb[j] = 0.f;
#pragma unroll
            for (int f = 0; f < 10; f++) s_se[j][f] = 0.f;
        } else {
            const float* ei = &s_emb[i * 11];
            const float* ej = &s_emb[j * 11];
            float dx = ej[0] - ei[0], dy = ej[1] - ei[1];
            float r = sqrtf(dx * dx + dy * dy);
            float hx = ei[2], hy = ei[3];
            float hr = sqrtf(hx * hx + hy * hy);
            float inv = 1.f / (r * hr);
            float se[10];
            se[0] = r * (1.f / 12.f);
            se[1] = (dx * hx + dy * hy) * inv;
            se[2] = (dy * hx - dx * hy) * inv;
            se[3] = ej[2]; se[4] = ej[3];
            se[5] = ej[7]; se[6] = ej[8];
            float gx = ej[9] - ei[0], gy = ej[10] - ei[1];
            float gr = sqrtf(gx * gx + gy * gy);
            float ginv = 1.f / (gr * hr);
            se[7] = gr;
            se[8] = (gx * hx + gy * hy) * ginv;
            se[9] = (gy * hx - gx * hy) * ginv;
            float sc = 0.f;
#pragma unroll
            for (int f = 0; f < 10; f++) { s_se[j][f] = se[f]; sc += s_qk[f] * se[f]; }
            s_sc[j] = sc * 0.0625f;
            int jj = j - (j > i);
            out[OFF_UNN + (long)a * NE + jj] = r;
        }
    }
    __syncthreads();

    {
        int jb = warp * 4;
        float e[4][7];
#pragma unroll
        for (int jj = 0; jj < 4; jj++)
#pragma unroll
            for (int f = 0; f < 7; f++) e[jj][f] = s_se[jb + jj][f];
        float acc0[4] = {0.f, 0.f, 0.f, 0.f}, acc1[4] = {0.f, 0.f, 0.f, 0.f};
#pragma unroll
        for (int t = 0; t < 8; t++) {
            int o = lane + t * 32;
            float base = s_base[o];
            const float* we = &s_WE[o * 7];
            float w0 = we[0], w1 = we[1], w2 = we[2], w3 = we[3],
                  w4 = we[4], w5 = we[5], w6 = we[6];
            float W2a = s_W2[o], W2b = s_W2[DD + o];
#pragma unroll
            for (int jj = 0; jj < 4; jj++) {
                float pre = base + w0 * e[jj][0] + w1 * e[jj][1] + w2 * e[jj][2]
                          + w3 * e[jj][3] + w4 * e[jj][4] + w5 * e[jj][5] + w6 * e[jj][6];
                float rr = fmaxf(pre, 0.f);
                acc0[jj] += W2a * rr;
                acc1[jj] += W2b * rr;
            }
        }
#pragma unroll
        for (int jj = 0; jj < 4; jj++) {
            for (int o = 16; o; o >>= 1) {
                acc0[jj] += __shfl_down_sync(0xffffffffu, acc0[jj], o);
                acc1[jj] += __shfl_down_sync(0xffffffffu, acc1[jj], o);
            }
        }
        if (lane == 0) {
#pragma unroll
            for (int jj = 0; jj < 4; jj++) {
                int j = jb + jj;
                if (j == i) continue;
                float l0 = acc0[jj] + s_b2[0], l1 = acc1[jj] + s_b2[1];
                int jx = j - (j > i);
                long gidx = ((long)a * NE + jx) * 2;
                float u0 = gum[gidx], u1 = gum[gidx + 1];
                float g0 = -logf(-logf(u0 + 1e-10f) + 1e-10f);
                float g1 = -logf(-logf(u1 + 1e-10f) + 1e-10f);
                float z0 = (l0 + g0) * 2.f, z1 = (l1 + g1) * 2.f;
                float zm = fmaxf(z0, z1);
                float x0 = expf(z0 - zm), x1 = expf(z1 - zm);
                float p1 = x1 / (x0 + x1);
                s_hw[j] = p1;
                out[OFF_LOG + (long)a * NE + jx] = l1;
                out[OFF_HW + (long)a * NE + jx] = p1;
            }
        }
    }
    __syncthreads();

    if (tid < NAG) {
        float sc = s_sc[tid];
        float m = sc;
        for (int o = 16; o; o >>= 1) m = fmaxf(m, __shfl_xor_sync(0xffffffffu, m, o));
        float ev = (tid == i) ? 0.f : expf(sc - m);
        float sum = ev;
        for (int o = 16; o; o >>= 1) sum += __shfl_xor_sync(0xffffffffu, sum, o);
        float sw = ev / sum;
        float cb = sw * s_hw[tid];
        s_cb[tid] = cb;
        float csum = cb;
        for (int o = 16; o; o >>= 1) csum += __shfl_xor_sync(0xffffffffu, csum, o);
        float cwn = cb / (csum + 1e-6f);
        float ent = (tid == i) ? 0.f : (-cwn * logf(cwn + 1e-6f));
        for (int o = 16; o; o >>= 1) ent += __shfl_xor_sync(0xffffffffu, ent, o);
        if (tid == 0) g_ENT[a] = ent;
        if (tid != i) out[OFF_CMB + (long)a * NE + (tid - (tid > i))] = cb;
    }
    __syncthreads();

    {
        int o = tid;
        float vb = s_vb[o];
        float vw[10];
#pragma unroll
        for (int f = 0; f < 10; f++) vw[f] = s_VW[o * 10 + f];
        float acc = 0.f;
#pragma unroll 4
        for (int j = 0; j < NAG; j++) {
            float c = s_cb[j];
            float4 p0 = *(const float4*)&s_se[j][0];
            float4 p1 = *(const float4*)&s_se[j][4];
            float4 p2 = *(const float4*)&s_se[j][8];
            float vv = vb;
            vv += vw[0] * p0.x + vw[1] * p0.y + vw[2] * p0.z + vw[3] * p0.w;
            vv += vw[4] * p1.x + vw[5] * p1.y + vw[6] * p1.z + vw[7] * p1.w;
            vv += vw[8] * p2.x + vw[9] * p2.y;
            acc += c * fmaxf(vv, 0.f);
        }
        bf16 h, m;
        split2(acc, h, m);
        long idx = (long)a * 512 + 256 + o;
        g_FINh[idx] = h; g_FINm[idx] = m;
    }
}

// ------- deterministic entropy reduction -------
__global__ void ent_reduce(const float* __restrict__ ent, float* __restrict__ out)
{
    __shared__ float s[256];
    float v = 0.f;
    for (int k = threadIdx.x; k < NA; k += 256) v += ent[k];
    s[threadIdx.x] = v;
    __syncthreads();
    for (int o = 128; o; o >>= 1) {
        if (threadIdx.x < o) s[threadIdx.x] += s[threadIdx.x + o];
        __syncthreads();
    }
    if (threadIdx.x == 0) out[0] = s[0] * (1.f / 4096.f);
}

extern "C" void kernel_launch(void* const* d_in, const int* in_sizes, int n_in,
                              void* d_out, int out_size)
{
    const float* emb   = (const float*)d_in[0];
    const float* gum   = (const float*)d_in[1];
    const float* emb1w = (const float*)d_in[2];
    const float* emb1b = (const float*)d_in[3];
    const float* emb2w = (const float*)d_in[4];
    const float* emb2b = (const float*)d_in[5];
    const float* hm1w  = (const float*)d_in[6];
    const float* hm1b  = (const float*)d_in[7];
    const float* hm2w  = (const float*)d_in[8];
    const float* hm2b  = (const float*)d_in[9];
    const float* hew   = (const float*)d_in[10];
    const float* heb   = (const float*)d_in[11];
    const float* qw    = (const float*)d_in[12];
    const float* kw    = (const float*)d_in[13];
    const float* vw    = (const float*)d_in[14];
    const float* vb    = (const float*)d_in[15];
    const float* decw  = (const float*)d_in[16];
    const float* decb  = (const float*)d_in[17];
    float* out = (float*)d_out;

    bf16 *pH1h, *pH1m, *pFh, *pFm;
    bf16 *pWeh, *pWem, *pWhh, *pWhm, *pWdh, *pWdm;
    float *pAE, *pBASE, *pENT;
    cudaGetSymbolAddress((void**)&pH1h, g_H1h);
    cudaGetSymbolAddress((void**)&pH1m, g_H1m);
    cudaGetSymbolAddress((void**)&pFh, g_FINh);
    cudaGetSymbolAddress((void**)&pFm, g_FINm);
    cudaGetSymbolAddress((void**)&pWeh, g_Weh);
    cudaGetSymbolAddress((void**)&pWem, g_Wem);
    cudaGetSymbolAddress((void**)&pWhh, g_Whh);
    cudaGetSymbolAddress((void**)&pWhm, g_Whm);
    cudaGetSymbolAddress((void**)&pWdh, g_Wdh);
    cudaGetSymbolAddress((void**)&pWdm, g_Wdm);
    cudaGetSymbolAddress((void**)&pAE, g_AE);
    cudaGetSymbolAddress((void**)&pBASE, g_BASE);
    cudaGetSymbolAddress((void**)&pENT, g_ENT);

    packW_kernel<<<1408, 256>>>(emb2w, hm1w, decw);
    h1_kernel<<<NA / 2, 256>>>(emb, emb1w, emb1b);
    foldA_kernel<<<8, 256>>>(hew, hm2w, hm2b, qw, kw);
    foldB_kernel<<<13, 256>>>(heb);

    // AE = leaky(H1 @ emb2_w^T + b) -> float g_AE + split FIN[:,0:256]
    gemm_bf<2, 1><<<dim3(4, 64), 256>>>(pH1h, pH1m, 128, pWeh, pWem, 128,
                                        emb2b, pAE, 256, pFh, pFm, 512, 128);
    // BASE = AE @ hm1_w[:,:256]^T + hm1_b (A = split FIN cols 0-255)
    gemm_bf<0, 0><<<dim3(4, 64), 256>>>(pFh, pFm, 512, pWhh, pWhm, 256,
                                        hm1b, pBASE, 256, nullptr, nullptr, 0, 256);
    // fused edge pipeline; writes split FIN[:,256:512] + 4 outputs
    edge_kernel<<<NA, 256>>>(emb, gum, hm1w, vw, vb, out);
    // output = FIN @ dec_w^T + dec_b
    gemm_bf<0, 0><<<dim3(8, 64), 256>>>(pFh, pFm, 512, pWdh, pWdm, 512,
                                        decb, out, 512, nullptr, nullptr, 0, 512);
    ent_reduce<<<1, 256>>>(pENT, out + OFF_ENT);
}

// round 11
// speedup vs baseline: 1.5979x; 1.5979x over previous
#include <cuda_runtime.h>
#include <cuda_bf16.h>
#include <stdint.h>
#include <math.h>

#define BLK 256
#define NAG 32
#define NA  4096
#define DD  256
#define NE  31

#define OFF_LOG 2097152L
#define OFF_UNN 2224128L
#define OFF_ENT 2351104L
#define OFF_HW  2351105L
#define OFF_CMB 2478081L

typedef __nv_bfloat16 bf16;

// ------- scratch: bf16 (hi, mid) planes for all GEMM operands -------
__device__ __align__(16) bf16 g_H1h[NA * 128], g_H1m[NA * 128];
__device__ __align__(16) bf16 g_FINh[NA * 512], g_FINm[NA * 512];   // [AE | X]
__device__ __align__(16) bf16 g_Weh[256 * 128], g_Wem[256 * 128];
__device__ __align__(16) bf16 g_Whh[256 * 256], g_Whm[256 * 256];
__device__ __align__(16) bf16 g_Wdh[512 * 512], g_Wdm[512 * 512];
__device__ float g_AE[NA * DD];
__device__ float g_BASE[NA * DD];
__device__ float g_ENT[NA];
__device__ float g_W2e[2 * DD];
__device__ float g_b2e[2];
__device__ float g_QKW[DD * 10];
__device__ float g_pW2e[8 * 512];
__device__ float g_pQKW[8 * DD * 10];
__device__ float g_pb2e[16];

// ------- bf16 2-way split -------
__device__ __forceinline__ void split2(float x, bf16& h, bf16& m) {
    h = __float2bfloat16_rn(x);
    m = __float2bfloat16_rn(x - __bfloat162float(h));
}

// ------- bf16 m16n8k16 MMA (legacy HMMA; supported on plain sm_103) -------
__device__ __forceinline__ void mma_bf16(float* d, const uint32_t* a,
                                         uint32_t b0, uint32_t b1) {
    asm volatile(
        "mma.sync.aligned.m16n8k16.row.col.f32.bf16.bf16.f32 "
        "{%0,%1,%2,%3}, {%4,%5,%6,%7}, {%8,%9}, {%0,%1,%2,%3};\n"
        : "+f"(d[0]), "+f"(d[1]), "+f"(d[2]), "+f"(d[3])
        : "r"(a[0]), "r"(a[1]), "r"(a[2]), "r"(a[3]), "r"(b0), "r"(b1));
}
__device__ __forceinline__ void cpa16(uint32_t s, const void* g) {
    asm volatile("cp.async.cg.shared.global [%0], [%1], 16;" :: "r"(s), "l"(g));
}

// ------- bf16-split tensor GEMM, cp.async double-buffered --------------
// C = act(A[MxK] @ W[NxK]^T + bias).  BM=BN=64, BK=32, 256 threads,
// 8 warps 4(m)x2(n), warp tile 16x32.  3 passes: hh + mh + hm.
// Smem rows: 32 bf16 = 16 words, padded to 20 (16B-aligned chunks,
// conflict-free fragment LDS).  Requires M%64==0, N%64==0, K%32==0.
#define SSTR 20
template <int ACT, int PACK>
__global__ void __launch_bounds__(256)
gemm_bf(const bf16* __restrict__ Ah, const bf16* __restrict__ Am, int lda,
        const bf16* __restrict__ Wh, const bf16* __restrict__ Wm, int ldw,
        const float* __restrict__ bias, float* __restrict__ C, int ldc,
        bf16* __restrict__ Cph, bf16* __restrict__ Cpm, int ldcp, int K)
{
    // [stage][array: Ah,Am,Bh,Bm][row*SSTR + word]
    __shared__ __align__(16) uint32_t SM[2][4][64 * SSTR];
    uint32_t sbase = (uint32_t)__cvta_generic_to_shared(&SM[0][0][0]);

    int tid = threadIdx.x;
    int lane = tid & 31, wid = tid >> 5;
    int g = lane >> 2, tig = lane & 3;
    int wm = wid >> 1, wn = wid & 1;
    int bm = blockIdx.y * 64, bn = blockIdx.x * 64;

    float acc[4][4];
#pragma unroll
    for (int nt = 0; nt < 4; nt++)
#pragma unroll
        for (int q = 0; q < 4; q++) acc[nt][q] = 0.f;

    // staging: 256 threads cover 64 rows x 4 chunks (16B = 8 bf16 each)
    int sr = tid >> 2, sc = tid & 3;
    const bf16* pAh = Ah + (size_t)(bm + sr) * lda + sc * 8;
    const bf16* pAm = Am + (size_t)(bm + sr) * lda + sc * 8;
    const bf16* pWh = Wh + (size_t)(bn + sr) * ldw + sc * 8;
    const bf16* pWm = Wm + (size_t)(bn + sr) * ldw + sc * 8;
    uint32_t dbase = sbase + (uint32_t)(sr * SSTR * 4 + sc * 16);
    const uint32_t ARR = 64 * SSTR * 4;   // bytes per array
    const uint32_t STG = 4 * ARR;         // bytes per stage

    int nk = K / 32;
    // prologue: stages 0 and 1 in flight
    {
        cpa16(dbase + 0 * ARR, pAh);
        cpa16(dbase + 1 * ARR, pAm);
        cpa16(dbase + 2 * ARR, pWh);
        cpa16(dbase + 3 * ARR, pWm);
        asm volatile("cp.async.commit_group;");
        if (nk > 1) {
            cpa16(dbase + STG + 0 * ARR, pAh + 32);
            cpa16(dbase + STG + 1 * ARR, pAm + 32);
            cpa16(dbase + STG + 2 * ARR, pWh + 32);
            cpa16(dbase + STG + 3 * ARR, pWm + 32);
        }
        asm volatile("cp.async.commit_group;");
    }

    for (int t = 0; t < nk; t++) {
        asm volatile("cp.async.wait_group 1;");
        __syncthreads();
        int s = t & 1;
        const uint32_t* sAh = &SM[s][0][0];
        const uint32_t* sAm = &SM[s][1][0];
        const uint32_t* sBh = &SM[s][2][0];
        const uint32_t* sBm = &SM[s][3][0];
        int ar = (wm * 16 + g) * SSTR;
#pragma unroll
        for (int ks = 0; ks < 2; ks++) {
            int kw = ks * 8;
            uint32_t ah[4] = {sAh[ar + kw + tig], sAh[ar + 8 * SSTR + kw + tig],
                              sAh[ar + kw + tig + 4], sAh[ar + 8 * SSTR + kw + tig + 4]};
            uint32_t am[4] = {sAm[ar + kw + tig], sAm[ar + 8 * SSTR + kw + tig],
                              sAm[ar + kw + tig + 4], sAm[ar + 8 * SSTR + kw + tig + 4]};
#pragma unroll
            for (int nt = 0; nt < 4; nt++) {
                int br = (wn * 32 + nt * 8 + g) * SSTR;
                uint32_t bh0 = sBh[br + kw + tig], bh1 = sBh[br + kw + tig + 4];
                uint32_t bm0 = sBm[br + kw + tig], bm1 = sBm[br + kw + tig + 4];
                mma_bf16(acc[nt], ah, bh0, bh1);   // hi*hi
                mma_bf16(acc[nt], am, bh0, bh1);   // mid*hi
                mma_bf16(acc[nt], ah, bm0, bm1);   // hi*mid
            }
        }
        __syncthreads();
        if (t + 2 < nk) {
            int k0 = (t + 2) * 32;
            uint32_t db = dbase + (uint32_t)s * STG;
            cpa16(db + 0 * ARR, pAh + k0);
            cpa16(db + 1 * ARR, pAm + k0);
            cpa16(db + 2 * ARR, pWh + k0);
            cpa16(db + 3 * ARR, pWm + k0);
        }
        asm volatile("cp.async.commit_group;");
    }

    // epilogue: c0:(g,2t) c1:(g,2t+1) c2:(g+8,2t) c3:(g+8,2t+1)
    long gm0 = bm + wm * 16 + g;
    long gm1 = gm0 + 8;
#pragma unroll
    for (int nt = 0; nt < 4; nt++) {
        long gn = bn + wn * 32 + nt * 8 + 2 * tig;
        float b0 = bias[gn], b1 = bias[gn + 1];
        float v00 = acc[nt][0] + b0, v01 = acc[nt][1] + b1;
        float v10 = acc[nt][2] + b0, v11 = acc[nt][3] + b1;
        if (ACT == 1) {
            v00 = fmaxf(v00, 0.f); v01 = fmaxf(v01, 0.f);
            v10 = fmaxf(v10, 0.f); v11 = fmaxf(v11, 0.f);
        }
        if (ACT == 2) {
            v00 = v00 > 0.f ? v00 : 0.01f * v00;
            v01 = v01 > 0.f ? v01 : 0.01f * v01;
            v10 = v10 > 0.f ? v10 : 0.01f * v10;
            v11 = v11 > 0.f ? v11 : 0.01f * v11;
        }
        *(float2*)&C[gm0 * ldc + gn] = make_float2(v00, v01);
        *(float2*)&C[gm1 * ldc + gn] = make_float2(v10, v11);
        if (PACK) {
            bf16 h, m;
            split2(v00, h, m); Cph[gm0 * ldcp + gn] = h;     Cpm[gm0 * ldcp + gn] = m;
            split2(v01, h, m); Cph[gm0 * ldcp + gn + 1] = h; Cpm[gm0 * ldcp + gn + 1] = m;
            split2(v10, h, m); Cph[gm1 * ldcp + gn] = h;     Cpm[gm1 * ldcp + gn] = m;
            split2(v11, h, m); Cph[gm1 * ldcp + gn + 1] = h; Cpm[gm1 * ldcp + gn + 1] = m;
        }
    }
}

// ------- weight pre-pack (2-way bf16 split) -------
__global__ void packW_kernel(const float* __restrict__ emb2w,
                             const float* __restrict__ hm1w,
                             const float* __restrict__ decw)
{
    int i = blockIdx.x * 256 + threadIdx.x;
    bf16 h, m;
    if (i < 32768) {
        split2(emb2w[i], h, m);
        g_Weh[i] = h; g_Wem[i] = m;
    } else if (i < 98304) {
        int j = i - 32768;
        split2(hm1w[(j >> 8) * 263 + (j & 255)], h, m);
        g_Whh[j] = h; g_Whm[j] = m;
    } else if (i < 360448) {
        int j = i - 98304;
        split2(decw[j], h, m);
        g_Wdh[j] = h; g_Wdm[j] = m;
    }
}

// ------- fold stage A -------
__global__ void foldA_kernel(const float* __restrict__ he_w,
                             const float* __restrict__ hm2_w, const float* __restrict__ hm2_b,
                             const float* __restrict__ q_w, const float* __restrict__ k_w)
{
    int p = blockIdx.x;
    int t = threadIdx.x;
    float s0 = 0.f, s1 = 0.f;
#pragma unroll 8
    for (int m = 0; m < 32; m++) {
        int mm = p * 32 + m;
        float w2 = hm2_w[mm * DD + t];
        s0 += he_w[mm] * w2;
        s1 += he_w[DD + mm] * w2;
    }
    g_pW2e[p * 512 + t] = s0;
    g_pW2e[p * 512 + 256 + t] = s1;

    float acc[10];
#pragma unroll
    for (int f = 0; f < 10; f++) acc[f] = 0.f;
#pragma unroll 4
    for (int d = 0; d < 32; d++) {
        int dd = p * 32 + d;
        float qv = q_w[dd * DD + t];
#pragma unroll
        for (int f = 0; f < 10; f++) acc[f] += qv * k_w[dd * 10 + f];
    }
#pragma unroll
    for (int f = 0; f < 10; f++) g_pQKW[(p * DD + t) * 10 + f] = acc[f];

    if (t < 2) {
        float s = 0.f;
        for (int m = 0; m < 32; m++) {
            int mm = p * 32 + m;
            s += he_w[t * DD + mm] * hm2_b[mm];
        }
        g_pb2e[p * 2 + t] = s;
    }
}

// ------- fold stage B: wide combine -------
__global__ void foldB_kernel(const float* __restrict__ he_b)
{
    int idx = blockIdx.x * 256 + threadIdx.x;
    if (idx < 512) {
        float s = 0.f;
#pragma unroll
        for (int p = 0; p < 8; p++) s += g_pW2e[p * 512 + idx];
        g_W2e[idx] = s;
    } else if (idx < 3072) {
        int j = idx - 512;
        float s = 0.f;
#pragma unroll
        for (int p = 0; p < 8; p++) s += g_pQKW[p * 2560 + j];
        g_QKW[j] = s;
    } else if (idx < 3074) {
        int t = idx - 3072;
        float s = he_b[t];
#pragma unroll
        for (int p = 0; p < 8; p++) s += g_pb2e[p * 2 + t];
        g_b2e[t] = s;
    }
}

// ------- H1 = leaky(emb[:,4:9] @ emb1_w^T + b), split output -------
__global__ void h1_kernel(const float* __restrict__ emb,
                          const float* __restrict__ w, const float* __restrict__ b)
{
    __shared__ float sw[128 * 5];
    __shared__ float sb2[128];
    int tid = threadIdx.x;
    for (int e = tid; e < 640; e += 256) sw[e] = w[e];
    if (tid < 128) sb2[tid] = b[tid];
    __syncthreads();
    int r = blockIdx.x * 2 + (tid >> 7);
    int c = tid & 127;
    const float* er = emb + (long)r * 11 + 4;
    float e0 = er[0], e1 = er[1], e2 = er[2], e3 = er[3], e4 = er[4];
    const float* wc = &sw[c * 5];
    float v = sb2[c] + e0 * wc[0] + e1 * wc[1] + e2 * wc[2] + e3 * wc[3] + e4 * wc[4];
    v = v > 0.f ? v : 0.01f * v;
    bf16 h, m;
    split2(v, h, m);
    long idx = (long)r * 128 + c;
    g_H1h[idx] = h; g_H1m[idx] = m;
}

// ------- fused per-agent edge kernel -------
#define SEP 12
__global__ void edge_kernel(const float* __restrict__ emb,
                            const float* __restrict__ gum,
                            const float* __restrict__ hm1_w,
                            const float* __restrict__ v_w,
                            const float* __restrict__ v_b,
                            float* __restrict__ out)
{
    int a = blockIdx.x;
    int bb = a >> 5, i = a & 31;
    int tid = threadIdx.x;
    int lane = tid & 31, warp = tid >> 5;

    __shared__ float s_emb[NAG * 11];
    __shared__ float s_WE[DD * 7];
    __shared__ float s_W2[2 * DD];
    __shared__ float s_b2[2];
    __shared__ float s_VW[DD * 10];
    __shared__ float s_vb[DD];
    __shared__ float s_base[DD];
    __shared__ float s_qk[10];
    __shared__ __align__(16) float s_se[NAG][SEP];
    __shared__ float s_sc[NAG];
    __shared__ float s_hw[NAG];
    __shared__ float s_cb[NAG];
    __shared__ float s_red[8 * 10];

    for (int e = tid; e < NAG * 11; e += BLK) s_emb[e] = emb[bb * NAG * 11 + e];
    for (int e = tid; e < DD * 7; e += BLK) s_WE[e] = hm1_w[(e / 7) * 263 + 256 + (e % 7)];
    s_W2[tid] = g_W2e[tid];
    s_W2[DD + tid] = g_W2e[DD + tid];
    for (int e = tid; e < DD * 10; e += BLK) s_VW[e] = v_w[e];
    s_vb[tid] = v_b[tid];
    s_base[tid] = g_BASE[(long)a * DD + tid];
    if (tid < 2) s_b2[tid] = g_b2e[tid];

    float av = g_AE[(long)a * DD + tid];
#pragma unroll
    for (int f = 0; f < 10; f++) {
        float p = av * g_QKW[tid * 10 + f];
        for (int o = 16; o; o >>= 1) p += __shfl_down_sync(0xffffffffu, p, o);
        if (lane == 0) s_red[warp * 10 + f] = p;
    }
    __syncthreads();
    if (tid < 10) {
        float s = 0.f;
        for (int w = 0; w < 8; w++) s += s_red[w * 10 + tid];
        s_qk[tid] = s;
    }
    __syncthreads();

    if (tid < NAG) {
        int j = tid;
        s_se[j][10] = 0.f; s_se[j][11] = 0.f;
        if (j == i) {
            s_sc[j] = -1e30f; s_hw[j] = 0.f; s_cb[j] = 0.f;
#pragma unroll
            for (int f = 0; f < 10; f++) s_se[j][f] = 0.f;
        } else {
            const float* ei = &s_emb[i * 11];
            const float* ej = &s_emb[j * 11];
            float dx = ej[0] - ei[0], dy = ej[1] - ei[1];
            float r = sqrtf(dx * dx + dy * dy);
            float hx = ei[2], hy = ei[3];
            float hr = sqrtf(hx * hx + hy * hy);
            float inv = 1.f / (r * hr);
            float se[10];
            se[0] = r * (1.f / 12.f);
            se[1] = (dx * hx + dy * hy) * inv;
            se[2] = (dy * hx - dx * hy) * inv;
            se[3] = ej[2]; se[4] = ej[3];
            se[5] = ej[7]; se[6] = ej[8];
            float gx = ej[9] - ei[0], gy = ej[10] - ei[1];
            float gr = sqrtf(gx * gx + gy * gy);
            float ginv = 1.f / (gr * hr);
            se[7] = gr;
            se[8] = (gx * hx + gy * hy) * ginv;
            se[9] = (gy * hx - gx * hy) * ginv;
            float sc = 0.f;
#pragma unroll
            for (int f = 0; f < 10; f++) { s_se[j][f] = se[f]; sc += s_qk[f] * se[f]; }
            s_sc[j] = sc * 0.0625f;
            int jj = j - (j > i);
            out[OFF_UNN + (long)a * NE + jj] = r;
        }
    }
    __syncthreads();

    {
        int jb = warp * 4;
        float e[4][7];
#pragma unroll
        for (int jj = 0; jj < 4; jj++)
#pragma unroll
            for (int f = 0; f < 7; f++) e[jj][f] = s_se[jb + jj][f];
        float acc0[4] = {0.f, 0.f, 0.f, 0.f}, acc1[4] = {0.f, 0.f, 0.f, 0.f};
#pragma unroll
        for (int t = 0; t < 8; t++) {
            int o = lane + t * 32;
            float base = s_base[o];
            const float* we = &s_WE[o * 7];
            float w0 = we[0], w1 = we[1], w2 = we[2], w3 = we[3],
                  w4 = we[4], w5 = we[5], w6 = we[6];
            float W2a = s_W2[o], W2b = s_W2[DD + o];
#pragma unroll
            for (int jj = 0; jj < 4; jj++) {
                float pre = base + w0 * e[jj][0] + w1 * e[jj][1] + w2 * e[jj][2]
                          + w3 * e[jj][3] + w4 * e[jj][4] + w5 * e[jj][5] + w6 * e[jj][6];
                float rr = fmaxf(pre, 0.f);
                acc0[jj] += W2a * rr;
                acc1[jj] += W2b * rr;
            }
        }
#pragma unroll
        for (int jj = 0; jj < 4; jj++) {
            for (int o = 16; o; o >>= 1) {
                acc0[jj] += __shfl_down_sync(0xffffffffu, acc0[jj], o);
                acc1[jj] += __shfl_down_sync(0xffffffffu, acc1[jj], o);
            }
        }
        if (lane == 0) {
#pragma unroll
            for (int jj = 0; jj < 4; jj++) {
                int j = jb + jj;
                if (j == i) continue;
                float l0 = acc0[jj] + s_b2[0], l1 = acc1[jj] + s_b2[1];
                int jx = j - (j > i);
                long gidx = ((long)a * NE + jx) * 2;
                float u0 = gum[gidx], u1 = gum[gidx + 1];
                float g0 = -logf(-logf(u0 + 1e-10f) + 1e-10f);
                float g1 = -logf(-logf(u1 + 1e-10f) + 1e-10f);
                float z0 = (l0 + g0) * 2.f, z1 = (l1 + g1) * 2.f;
                float zm = fmaxf(z0, z1);
                float x0 = expf(z0 - zm), x1 = expf(z1 - zm);
                float p1 = x1 / (x0 + x1);
                s_hw[j] = p1;
                out[OFF_LOG + (long)a * NE + jx] = l1;
                out[OFF_HW + (long)a * NE + jx] = p1;
            }
        }
    }
    __syncthreads();

    if (tid < NAG) {
        float sc = s_sc[tid];
        float m = sc;
        for (int o = 16; o; o >>= 1) m = fmaxf(m, __shfl_xor_sync(0xffffffffu, m, o));
        float ev = (tid == i) ? 0.f : expf(sc - m);
        float sum = ev;
        for (int o = 16; o; o >>= 1) sum += __shfl_xor_sync(0xffffffffu, sum, o);
        float sw = ev / sum;
        float cb = sw * s_hw[tid];
        s_cb[tid] = cb;
        float csum = cb;
        for (int o = 16; o; o >>= 1) csum += __shfl_xor_sync(0xffffffffu, csum, o);
        float cwn = cb / (csum + 1e-6f);
        float ent = (tid == i) ? 0.f : (-cwn * logf(cwn + 1e-6f));
        for (int o = 16; o; o >>= 1) ent += __shfl_xor_sync(0xffffffffu, ent, o);
        if (tid == 0) g_ENT[a] = ent;
        if (tid != i) out[OFF_CMB + (long)a * NE + (tid - (tid > i))] = cb;
    }
    __syncthreads();

    {
        int o = tid;
        float vb = s_vb[o];
        float vw[10];
#pragma unroll
        for (int f = 0; f < 10; f++) vw[f] = s_VW[o * 10 + f];
        float acc = 0.f;
#pragma unroll 4
        for (int j = 0; j < NAG; j++) {
            float c = s_cb[j];
            float4 p0 = *(const float4*)&s_se[j][0];
            float4 p1 = *(const float4*)&s_se[j][4];
            float4 p2 = *(const float4*)&s_se[j][8];
            float vv = vb;
            vv += vw[0] * p0.x + vw[1] * p0.y + vw[2] * p0.z + vw[3] * p0.w;
            vv += vw[4] * p1.x + vw[5] * p1.y + vw[6] * p1.z + vw[7] * p1.w;
            vv += vw[8] * p2.x + vw[9] * p2.y;
            acc += c * fmaxf(vv, 0.f);
        }
        bf16 h, m;
        split2(acc, h, m);
        long idx = (long)a * 512 + 256 + o;
        g_FINh[idx] = h; g_FINm[idx] = m;
    }
}

// ------- deterministic entropy reduction -------
__global__ void ent_reduce(const float* __restrict__ ent, float* __restrict__ out)
{
    __shared__ float s[256];
    float v = 0.f;
    for (int k = threadIdx.x; k < NA; k += 256) v += ent[k];
    s[threadIdx.x] = v;
    __syncthreads();
    for (int o = 128; o; o >>= 1) {
        if (threadIdx.x < o) s[threadIdx.x] += s[threadIdx.x + o];
        __syncthreads();
    }
    if (threadIdx.x == 0) out[0] = s[0] * (1.f / 4096.f);
}

extern "C" void kernel_launch(void* const* d_in, const int* in_sizes, int n_in,
                              void* d_out, int out_size)
{
    const float* emb   = (const float*)d_in[0];
    const float* gum   = (const float*)d_in[1];
    const float* emb1w = (const float*)d_in[2];
    const float* emb1b = (const float*)d_in[3];
    const float* emb2w = (const float*)d_in[4];
    const float* emb2b = (const float*)d_in[5];
    const float* hm1w  = (const float*)d_in[6];
    const float* hm1b  = (const float*)d_in[7];
    const float* hm2w  = (const float*)d_in[8];
    const float* hm2b  = (const float*)d_in[9];
    const float* hew   = (const float*)d_in[10];
    const float* heb   = (const float*)d_in[11];
    const float* qw    = (const float*)d_in[12];
    const float* kw    = (const float*)d_in[13];
    const float* vw    = (const float*)d_in[14];
    const float* vb    = (const float*)d_in[15];
    const float* decw  = (const float*)d_in[16];
    const float* decb  = (const float*)d_in[17];
    float* out = (float*)d_out;

    bf16 *pH1h, *pH1m, *pFh, *pFm;
    bf16 *pWeh, *pWem, *pWhh, *pWhm, *pWdh, *pWdm;
    float *pAE, *pBASE, *pENT;
    cudaGetSymbolAddress((void**)&pH1h, g_H1h);
    cudaGetSymbolAddress((void**)&pH1m, g_H1m);
    cudaGetSymbolAddress((void**)&pFh, g_FINh);
    cudaGetSymbolAddress((void**)&pFm, g_FINm);
    cudaGetSymbolAddress((void**)&pWeh, g_Weh);
    cudaGetSymbolAddress((void**)&pWem, g_Wem);
    cudaGetSymbolAddress((void**)&pWhh, g_Whh);
    cudaGetSymbolAddress((void**)&pWhm, g_Whm);
    cudaGetSymbolAddress((void**)&pWdh, g_Wdh);
    cudaGetSymbolAddress((void**)&pWdm, g_Wdm);
    cudaGetSymbolAddress((void**)&pAE, g_AE);
    cudaGetSymbolAddress((void**)&pBASE, g_BASE);
    cudaGetSymbolAddress((void**)&pENT, g_ENT);

    packW_kernel<<<1408, 256>>>(emb2w, hm1w, decw);
    h1_kernel<<<NA / 2, 256>>>(emb, emb1w, emb1b);
    foldA_kernel<<<8, 256>>>(hew, hm2w, hm2b, qw, kw);
    foldB_kernel<<<13, 256>>>(heb);

    // AE = leaky(H1 @ emb2_w^T + b) -> float g_AE + split FIN[:,0:256]
    gemm_bf<2, 1><<<dim3(4, 64), 256>>>(pH1h, pH1m, 128, pWeh, pWem, 128,
                                        emb2b, pAE, 256, pFh, pFm, 512, 128);
    // BASE = AE @ hm1_w[:,:256]^T + hm1_b (A = split FIN cols 0-255)
    gemm_bf<0, 0><<<dim3(4, 64), 256>>>(pFh, pFm, 512, pWhh, pWhm, 256,
                                        hm1b, pBASE, 256, nullptr, nullptr, 0, 256);
    // fused edge pipeline; writes split FIN[:,256:512] + 4 outputs
    edge_kernel<<<NA, 256>>>(emb, gum, hm1w, vw, vb, out);
    // output = FIN @ dec_w^T + dec_b
    gemm_bf<0, 0><<<dim3(8, 64), 256>>>(pFh, pFm, 512, pWdh, pWdm, 512,
                                        decb, out, 512, nullptr, nullptr, 0, 512);
    ent_reduce<<<1, 256>>>(pENT, out + OFF_ENT);
}

// round 12
// speedup vs baseline: 1.6569x; 1.0369x over previous
#include <cuda_runtime.h>
#include <cuda_bf16.h>
#include <stdint.h>
#include <math.h>

#define BLK 256
#define NAG 32
#define NA  4096
#define DD  256
#define NE  31

#define OFF_LOG 2097152L
#define OFF_UNN 2224128L
#define OFF_ENT 2351104L
#define OFF_HW  2351105L
#define OFF_CMB 2478081L

typedef __nv_bfloat16 bf16;

// ------- scratch: bf16 (hi, mid) planes for all GEMM operands -------
__device__ __align__(16) bf16 g_H1h[NA * 128], g_H1m[NA * 128];
__device__ __align__(16) bf16 g_FINh[NA * 512], g_FINm[NA * 512];   // [AE | X]
__device__ __align__(16) bf16 g_Weh[256 * 128], g_Wem[256 * 128];
__device__ __align__(16) bf16 g_Whh[256 * 256], g_Whm[256 * 256];
__device__ __align__(16) bf16 g_Wdh[512 * 512], g_Wdm[512 * 512];
__device__ float g_AE[NA * DD];
__device__ float g_BASE[NA * DD];
__device__ float g_ENT[NA];
__device__ float g_W2e[2 * DD];
__device__ float g_b2e[2];
__device__ float g_QKW[DD * 10];
__device__ float g_pW2e[8 * 512];
__device__ float g_pQKW[8 * DD * 10];
__device__ float g_pb2e[16];

// ------- bf16 2-way split -------
__device__ __forceinline__ void split2(float x, bf16& h, bf16& m) {
    h = __float2bfloat16_rn(x);
    m = __float2bfloat16_rn(x - __bfloat162float(h));
}

// ------- bf16 m16n8k16 MMA -------
__device__ __forceinline__ void mma_bf16(float* d, const uint32_t* a,
                                         uint32_t b0, uint32_t b1) {
    asm volatile(
        "mma.sync.aligned.m16n8k16.row.col.f32.bf16.bf16.f32 "
        "{%0,%1,%2,%3}, {%4,%5,%6,%7}, {%8,%9}, {%0,%1,%2,%3};\n"
        : "+f"(d[0]), "+f"(d[1]), "+f"(d[2]), "+f"(d[3])
        : "r"(a[0]), "r"(a[1]), "r"(a[2]), "r"(a[3]), "r"(b0), "r"(b1));
}
__device__ __forceinline__ void cpa16(uint32_t s, const void* g) {
    asm volatile("cp.async.cg.shared.global [%0], [%1], 16;" :: "r"(s), "l"(g));
}

// ------- bf16-split tensor GEMM, cp.async double-buffered --------------
// C = act(A[MxK] @ W[NxK]^T + bias).  BM=128, BN=64, BK=32, 256 threads,
// 8 warps 4(m)x2(n), warp tile 32x32.  3 passes: hh + mh + hm.
// Dynamic smem: 2 stages x [Ah(128x20w) Am Bh(64x20w) Bm] = 61440 B.
#define SSTR 20
#define AW   (128 * SSTR)
#define BW   (64 * SSTR)
#define STGW (2 * AW + 2 * BW)
#define GSM_BYTES (2 * STGW * 4)
template <int ACT, int PACK>
__global__ void __launch_bounds__(256)
gemm_bf(const bf16* __restrict__ Ah, const bf16* __restrict__ Am, int lda,
        const bf16* __restrict__ Wh, const bf16* __restrict__ Wm, int ldw,
        const float* __restrict__ bias, float* __restrict__ C, int ldc,
        bf16* __restrict__ Cph, bf16* __restrict__ Cpm, int ldcp, int K)
{
    extern __shared__ uint32_t SM[];
    uint32_t sbase = (uint32_t)__cvta_generic_to_shared(SM);

    int tid = threadIdx.x;
    int lane = tid & 31, wid = tid >> 5;
    int g = lane >> 2, tig = lane & 3;
    int wm = wid >> 1, wn = wid & 1;
    int bm = blockIdx.y * 128, bn = blockIdx.x * 64;

    float acc[2][4][4];
#pragma unroll
    for (int mt = 0; mt < 2; mt++)
#pragma unroll
        for (int nt = 0; nt < 4; nt++)
#pragma unroll
            for (int q = 0; q < 4; q++) acc[mt][nt][q] = 0.f;

    // staging: A planes 512 chunks each (2 iters/thread), B planes 256 (1 iter)
    int ar0 = tid >> 2, ac0 = tid & 3;          // B rows + A rows iter0
    int ar1 = (tid + 256) >> 2;                 // A rows iter1
    const bf16* pA0h = Ah + (size_t)(bm + ar0) * lda + ac0 * 8;
    const bf16* pA0m = Am + (size_t)(bm + ar0) * lda + ac0 * 8;
    const bf16* pA1h = Ah + (size_t)(bm + ar1) * lda + ac0 * 8;
    const bf16* pA1m = Am + (size_t)(bm + ar1) * lda + ac0 * 8;
    const bf16* pW0h = Wh + (size_t)(bn + ar0) * ldw + ac0 * 8;
    const bf16* pW0m = Wm + (size_t)(bn + ar0) * ldw + ac0 * 8;
    uint32_t o0 = (uint32_t)(ar0 * SSTR + ac0 * 4) * 4;
    uint32_t o1 = (uint32_t)(ar1 * SSTR + ac0 * 4) * 4;

    int nk = K / 32;
#define STAGE(s, k0) do {                                            \
        uint32_t db = sbase + (uint32_t)(s) * STGW * 4;              \
        cpa16(db + o0, pA0h + (k0));                                 \
        cpa16(db + o1, pA1h + (k0));                                 \
        cpa16(db + AW * 4 + o0, pA0m + (k0));                        \
        cpa16(db + AW * 4 + o1, pA1m + (k0));                        \
        cpa16(db + 2 * AW * 4 + o0, pW0h + (k0));                    \
        cpa16(db + (2 * AW + BW) * 4 + o0, pW0m + (k0));             \
    } while (0)

    STAGE(0, 0);
    asm volatile("cp.async.commit_group;");
    if (nk > 1) STAGE(1, 32);
    asm volatile("cp.async.commit_group;");

    for (int t = 0; t < nk; t++) {
        asm volatile("cp.async.wait_group 1;");
        __syncthreads();
        int s = t & 1;
        const uint32_t* sAh = SM + s * STGW;
        const uint32_t* sAm = sAh + AW;
        const uint32_t* sBh = sAh + 2 * AW;
        const uint32_t* sBm = sAh + 2 * AW + BW;
#pragma unroll
        for (int ks = 0; ks < 2; ks++) {
            int kw = ks * 8;
            uint32_t ah[2][4], am[2][4];
#pragma unroll
            for (int mt = 0; mt < 2; mt++) {
                int ar = (wm * 32 + mt * 16 + g) * SSTR;
                ah[mt][0] = sAh[ar + kw + tig];
                ah[mt][1] = sAh[ar + 8 * SSTR + kw + tig];
                ah[mt][2] = sAh[ar + kw + tig + 4];
                ah[mt][3] = sAh[ar + 8 * SSTR + kw + tig + 4];
                am[mt][0] = sAm[ar + kw + tig];
                am[mt][1] = sAm[ar + 8 * SSTR + kw + tig];
                am[mt][2] = sAm[ar + kw + tig + 4];
                am[mt][3] = sAm[ar + 8 * SSTR + kw + tig + 4];
            }
#pragma unroll
            for (int nt = 0; nt < 4; nt++) {
                int br = (wn * 32 + nt * 8 + g) * SSTR;
                uint32_t bh0 = sBh[br + kw + tig], bh1 = sBh[br + kw + tig + 4];
                uint32_t bm0 = sBm[br + kw + tig], bm1 = sBm[br + kw + tig + 4];
#pragma unroll
                for (int mt = 0; mt < 2; mt++) {
                    mma_bf16(acc[mt][nt], ah[mt], bh0, bh1);   // hi*hi
                    mma_bf16(acc[mt][nt], am[mt], bh0, bh1);   // mid*hi
                    mma_bf16(acc[mt][nt], ah[mt], bm0, bm1);   // hi*mid
                }
            }
        }
        __syncthreads();
        if (t + 2 < nk) STAGE(s, (t + 2) * 32);
        asm volatile("cp.async.commit_group;");
    }
#undef STAGE

    // epilogue
#pragma unroll
    for (int mt = 0; mt < 2; mt++) {
        long gm0 = bm + wm * 32 + mt * 16 + g;
        long gm1 = gm0 + 8;
#pragma unroll
        for (int nt = 0; nt < 4; nt++) {
            long gn = bn + wn * 32 + nt * 8 + 2 * tig;
            float b0 = bias[gn], b1 = bias[gn + 1];
            float v00 = acc[mt][nt][0] + b0, v01 = acc[mt][nt][1] + b1;
            float v10 = acc[mt][nt][2] + b0, v11 = acc[mt][nt][3] + b1;
            if (ACT == 1) {
                v00 = fmaxf(v00, 0.f); v01 = fmaxf(v01, 0.f);
                v10 = fmaxf(v10, 0.f); v11 = fmaxf(v11, 0.f);
            }
            if (ACT == 2) {
                v00 = v00 > 0.f ? v00 : 0.01f * v00;
                v01 = v01 > 0.f ? v01 : 0.01f * v01;
                v10 = v10 > 0.f ? v10 : 0.01f * v10;
                v11 = v11 > 0.f ? v11 : 0.01f * v11;
            }
            *(float2*)&C[gm0 * ldc + gn] = make_float2(v00, v01);
            *(float2*)&C[gm1 * ldc + gn] = make_float2(v10, v11);
            if (PACK) {
                bf16 h, m;
                split2(v00, h, m); Cph[gm0 * ldcp + gn] = h;     Cpm[gm0 * ldcp + gn] = m;
                split2(v01, h, m); Cph[gm0 * ldcp + gn + 1] = h; Cpm[gm0 * ldcp + gn + 1] = m;
                split2(v10, h, m); Cph[gm1 * ldcp + gn] = h;     Cpm[gm1 * ldcp + gn] = m;
                split2(v11, h, m); Cph[gm1 * ldcp + gn + 1] = h; Cpm[gm1 * ldcp + gn + 1] = m;
            }
        }
    }
}

// ------- weight pre-pack (2-way bf16 split) -------
__global__ void packW_kernel(const float* __restrict__ emb2w,
                             const float* __restrict__ hm1w,
                             const float* __restrict__ decw)
{
    int i = blockIdx.x * 256 + threadIdx.x;
    bf16 h, m;
    if (i < 32768) {
        split2(emb2w[i], h, m);
        g_Weh[i] = h; g_Wem[i] = m;
    } else if (i < 98304) {
        int j = i - 32768;
        split2(hm1w[(j >> 8) * 263 + (j & 255)], h, m);
        g_Whh[j] = h; g_Whm[j] = m;
    } else if (i < 360448) {
        int j = i - 98304;
        split2(decw[j], h, m);
        g_Wdh[j] = h; g_Wdm[j] = m;
    }
}

// ------- fold stage A -------
__global__ void foldA_kernel(const float* __restrict__ he_w,
                             const float* __restrict__ hm2_w, const float* __restrict__ hm2_b,
                             const float* __restrict__ q_w, const float* __restrict__ k_w)
{
    int p = blockIdx.x;
    int t = threadIdx.x;
    float s0 = 0.f, s1 = 0.f;
#pragma unroll 8
    for (int m = 0; m < 32; m++) {
        int mm = p * 32 + m;
        float w2 = hm2_w[mm * DD + t];
        s0 += he_w[mm] * w2;
        s1 += he_w[DD + mm] * w2;
    }
    g_pW2e[p * 512 + t] = s0;
    g_pW2e[p * 512 + 256 + t] = s1;

    float acc[10];
#pragma unroll
    for (int f = 0; f < 10; f++) acc[f] = 0.f;
#pragma unroll 4
    for (int d = 0; d < 32; d++) {
        int dd = p * 32 + d;
        float qv = q_w[dd * DD + t];
#pragma unroll
        for (int f = 0; f < 10; f++) acc[f] += qv * k_w[dd * 10 + f];
    }
#pragma unroll
    for (int f = 0; f < 10; f++) g_pQKW[(p * DD + t) * 10 + f] = acc[f];

    if (t < 2) {
        float s = 0.f;
        for (int m = 0; m < 32; m++) {
            int mm = p * 32 + m;
            s += he_w[t * DD + mm] * hm2_b[mm];
        }
        g_pb2e[p * 2 + t] = s;
    }
}

// ------- fold stage B: wide combine -------
__global__ void foldB_kernel(const float* __restrict__ he_b)
{
    int idx = blockIdx.x * 256 + threadIdx.x;
    if (idx < 512) {
        float s = 0.f;
#pragma unroll
        for (int p = 0; p < 8; p++) s += g_pW2e[p * 512 + idx];
        g_W2e[idx] = s;
    } else if (idx < 3072) {
        int j = idx - 512;
        float s = 0.f;
#pragma unroll
        for (int p = 0; p < 8; p++) s += g_pQKW[p * 2560 + j];
        g_QKW[j] = s;
    } else if (idx < 3074) {
        int t = idx - 3072;
        float s = he_b[t];
#pragma unroll
        for (int p = 0; p < 8; p++) s += g_pb2e[p * 2 + t];
        g_b2e[t] = s;
    }
}

// ------- H1 = leaky(emb[:,4:9] @ emb1_w^T + b), split output -------
__global__ void h1_kernel(const float* __restrict__ emb,
                          const float* __restrict__ w, const float* __restrict__ b)
{
    __shared__ float sw[128 * 5];
    __shared__ float sb2[128];
    int tid = threadIdx.x;
    for (int e = tid; e < 640; e += 256) sw[e] = w[e];
    if (tid < 128) sb2[tid] = b[tid];
    __syncthreads();
    int r = blockIdx.x * 2 + (tid >> 7);
    int c = tid & 127;
    const float* er = emb + (long)r * 11 + 4;
    float e0 = er[0], e1 = er[1], e2 = er[2], e3 = er[3], e4 = er[4];
    const float* wc = &sw[c * 5];
    float v = sb2[c] + e0 * wc[0] + e1 * wc[1] + e2 * wc[2] + e3 * wc[3] + e4 * wc[4];
    v = v > 0.f ? v : 0.01f * v;
    bf16 h, m;
    split2(v, h, m);
    long idx = (long)r * 128 + c;
    g_H1h[idx] = h; g_H1m[idx] = m;
}

// ------- fused per-agent edge kernel -------
#define SEP 12
__global__ void edge_kernel(const float* __restrict__ emb,
                            const float* __restrict__ gum,
                            const float* __restrict__ hm1_w,
                            const float* __restrict__ v_w,
                            const float* __restrict__ v_b,
                            float* __restrict__ out)
{
    int a = blockIdx.x;
    int bb = a >> 5, i = a & 31;
    int tid = threadIdx.x;
    int lane = tid & 31, warp = tid >> 5;

    __shared__ float s_emb[NAG * 11];
    __shared__ float s_WE[DD * 7];
    __shared__ float s_W2[2 * DD];
    __shared__ float s_b2[2];
    __shared__ float s_VW[DD * 10];
    __shared__ float s_vb[DD];
    __shared__ float s_base[DD];
    __shared__ float s_qk[10];
    __shared__ __align__(16) float s_se[NAG][SEP];
    __shared__ float s_sc[NAG];
    __shared__ float s_hw[NAG];
    __shared__ float s_cb[NAG];
    __shared__ float s_red[8 * 10];

    for (int e = tid; e < NAG * 11; e += BLK) s_emb[e] = emb[bb * NAG * 11 + e];
    for (int e = tid; e < DD * 7; e += BLK) s_WE[e] = hm1_w[(e / 7) * 263 + 256 + (e % 7)];
    s_W2[tid] = g_W2e[tid];
    s_W2[DD + tid] = g_W2e[DD + tid];
    for (int e = tid; e < DD * 10; e += BLK) s_VW[e] = v_w[e];
    s_vb[tid] = v_b[tid];
    s_base[tid] = g_BASE[(long)a * DD + tid];
    if (tid < 2) s_b2[tid] = g_b2e[tid];

    float av = g_AE[(long)a * DD + tid];
#pragma unroll
    for (int f = 0; f < 10; f++) {
        float p = av * g_QKW[tid * 10 + f];
        for (int o = 16; o; o >>= 1) p += __shfl_down_sync(0xffffffffu, p, o);
        if (lane == 0) s_red[warp * 10 + f] = p;
    }
    __syncthreads();
    if (tid < 10) {
        float s = 0.f;
        for (int w = 0; w < 8; w++) s += s_red[w * 10 + tid];
        s_qk[tid] = s;
    }
    __syncthreads();

    if (tid < NAG) {
        int j = tid;
        s_se[j][10] = 0.f; s_se[j][11] = 0.f;
        if (j == i) {
            s_sc[j] = -1e30f; s_hw[j] = 0.f; s_cb[j] = 0.f;
#pragma unroll
            for (int f = 0; f < 10; f++) s_se[j][f] = 0.f;
        } else {
            const float* ei = &s_emb[i * 11];
            const float* ej = &s_emb[j * 11];
            float dx = ej[0] - ei[0], dy = ej[1] - ei[1];
            float r = sqrtf(dx * dx + dy * dy);
            float hx = ei[2], hy = ei[3];
            float hr = sqrtf(hx * hx + hy * hy);
            float inv = 1.f / (r * hr);
            float se[10];
            se[0] = r * (1.f / 12.f);
            se[1] = (dx * hx + dy * hy) * inv;
            se[2] = (dy * hx - dx * hy) * inv;
            se[3] = ej[2]; se[4] = ej[3];
            se[5] = ej[7]; se[6] = ej[8];
            float gx = ej[9] - ei[0], gy = ej[10] - ei[1];
            float gr = sqrtf(gx * gx + gy * gy);
            float ginv = 1.f / (gr * hr);
            se[7] = gr;
            se[8] = (gx * hx + gy * hy) * ginv;
            se[9] = (gy * hx - gx * hy) * ginv;
            float sc = 0.f;
#pragma unroll
            for (int f = 0; f < 10; f++) { s_se[j][f] = se[f]; sc += s_qk[f] * se[f]; }
            s_sc[j] = sc * 0.0625f;
            int jj = j - (j > i);
            out[OFF_UNN + (long)a * NE + jj] = r;
        }
    }
    __syncthreads();

    {
        int jb = warp * 4;
        float e[4][7];
#pragma unroll
        for (int jj = 0; jj < 4; jj++)
#pragma unroll
            for (int f = 0; f < 7; f++) e[jj][f] = s_se[jb + jj][f];
        float acc0[4] = {0.f, 0.f, 0.f, 0.f}, acc1[4] = {0.f, 0.f, 0.f, 0.f};
#pragma unroll
        for (int t = 0; t < 8; t++) {
            int o = lane + t * 32;
            float base = s_base[o];
            const float* we = &s_WE[o * 7];
            float w0 = we[0], w1 = we[1], w2 = we[2], w3 = we[3],
                  w4 = we[4], w5 = we[5], w6 = we[6];
            float W2a = s_W2[o], W2b = s_W2[DD + o];
#pragma unroll
            for (int jj = 0; jj < 4; jj++) {
                float pre = base + w0 * e[jj][0] + w1 * e[jj][1] + w2 * e[jj][2]
                          + w3 * e[jj][3] + w4 * e[jj][4] + w5 * e[jj][5] + w6 * e[jj][6];
                float rr = fmaxf(pre, 0.f);
                acc0[jj] += W2a * rr;
                acc1[jj] += W2b * rr;
            }
        }
#pragma unroll
        for (int jj = 0; jj < 4; jj++) {
            for (int o = 16; o; o >>= 1) {
                acc0[jj] += __shfl_down_sync(0xffffffffu, acc0[jj], o);
                acc1[jj] += __shfl_down_sync(0xffffffffu, acc1[jj], o);
            }
        }
        if (lane == 0) {
#pragma unroll
            for (int jj = 0; jj < 4; jj++) {
                int j = jb + jj;
                if (j == i) continue;
                float l0 = acc0[jj] + s_b2[0], l1 = acc1[jj] + s_b2[1];
                int jx = j - (j > i);
                long gidx = ((long)a * NE + jx) * 2;
                float u0 = gum[gidx], u1 = gum[gidx + 1];
                float g0 = -logf(-logf(u0 + 1e-10f) + 1e-10f);
                float g1 = -logf(-logf(u1 + 1e-10f) + 1e-10f);
                float z0 = (l0 + g0) * 2.f, z1 = (l1 + g1) * 2.f;
                float zm = fmaxf(z0, z1);
                float x0 = expf(z0 - zm), x1 = expf(z1 - zm);
                float p1 = x1 / (x0 + x1);
                s_hw[j] = p1;
                out[OFF_LOG + (long)a * NE + jx] = l1;
                out[OFF_HW + (long)a * NE + jx] = p1;
            }
        }
    }
    __syncthreads();

    if (tid < NAG) {
        float sc = s_sc[tid];
        float m = sc;
        for (int o = 16; o; o >>= 1) m = fmaxf(m, __shfl_xor_sync(0xffffffffu, m, o));
        float ev = (tid == i) ? 0.f : expf(sc - m);
        float sum = ev;
        for (int o = 16; o; o >>= 1) sum += __shfl_xor_sync(0xffffffffu, sum, o);
        float sw = ev / sum;
        float cb = sw * s_hw[tid];
        s_cb[tid] = cb;
        float csum = cb;
        for (int o = 16; o; o >>= 1) csum += __shfl_xor_sync(0xffffffffu, csum, o);
        float cwn = cb / (csum + 1e-6f);
        float ent = (tid == i) ? 0.f : (-cwn * logf(cwn + 1e-6f));
        for (int o = 16; o; o >>= 1) ent += __shfl_xor_sync(0xffffffffu, ent, o);
        if (tid == 0) g_ENT[a] = ent;
        if (tid != i) out[OFF_CMB + (long)a * NE + (tid - (tid > i))] = cb;
    }
    __syncthreads();

    {
        int o = tid;
        float vb = s_vb[o];
        float vw[10];
#pragma unroll
        for (int f = 0; f < 10; f++) vw[f] = s_VW[o * 10 + f];
        float acc = 0.f;
#pragma unroll 4
        for (int j = 0; j < NAG; j++) {
            float c = s_cb[j];
            float4 p0 = *(const float4*)&s_se[j][0];
            float4 p1 = *(const float4*)&s_se[j][4];
            float4 p2 = *(const float4*)&s_se[j][8];
            float vv = vb;
            vv += vw[0] * p0.x + vw[1] * p0.y + vw[2] * p0.z + vw[3] * p0.w;
            vv += vw[4] * p1.x + vw[5] * p1.y + vw[6] * p1.z + vw[7] * p1.w;
            vv += vw[8] * p2.x + vw[9] * p2.y;
            acc += c * fmaxf(vv, 0.f);
        }
        bf16 h, m;
        split2(acc, h, m);
        long idx = (long)a * 512 + 256 + o;
        g_FINh[idx] = h; g_FINm[idx] = m;
    }
}

// ------- deterministic entropy reduction -------
__global__ void ent_reduce(const float* __restrict__ ent, float* __restrict__ out)
{
    __shared__ float s[256];
    float v = 0.f;
    for (int k = threadIdx.x; k < NA; k += 256) v += ent[k];
    s[threadIdx.x] = v;
    __syncthreads();
    for (int o = 128; o; o >>= 1) {
        if (threadIdx.x < o) s[threadIdx.x] += s[threadIdx.x + o];
        __syncthreads();
    }
    if (threadIdx.x == 0) out[0] = s[0] * (1.f / 4096.f);
}

extern "C" void kernel_launch(void* const* d_in, const int* in_sizes, int n_in,
                              void* d_out, int out_size)
{
    const float* emb   = (const float*)d_in[0];
    const float* gum   = (const float*)d_in[1];
    const float* emb1w = (const float*)d_in[2];
    const float* emb1b = (const float*)d_in[3];
    const float* emb2w = (const float*)d_in[4];
    const float* emb2b = (const float*)d_in[5];
    const float* hm1w  = (const float*)d_in[6];
    const float* hm1b  = (const float*)d_in[7];
    const float* hm2w  = (const float*)d_in[8];
    const float* hm2b  = (const float*)d_in[9];
    const float* hew   = (const float*)d_in[10];
    const float* heb   = (const float*)d_in[11];
    const float* qw    = (const float*)d_in[12];
    const float* kw    = (const float*)d_in[13];
    const float* vw    = (const float*)d_in[14];
    const float* vb    = (const float*)d_in[15];
    const float* decw  = (const float*)d_in[16];
    const float* decb  = (const float*)d_in[17];
    float* out = (float*)d_out;

    bf16 *pH1h, *pH1m, *pFh, *pFm;
    bf16 *pWeh, *pWem, *pWhh, *pWhm, *pWdh, *pWdm;
    float *pAE, *pBASE, *pENT;
    cudaGetSymbolAddress((void**)&pH1h, g_H1h);
    cudaGetSymbolAddress((void**)&pH1m, g_H1m);
    cudaGetSymbolAddress((void**)&pFh, g_FINh);
    cudaGetSymbolAddress((void**)&pFm, g_FINm);
    cudaGetSymbolAddress((void**)&pWeh, g_Weh);
    cudaGetSymbolAddress((void**)&pWem, g_Wem);
    cudaGetSymbolAddress((void**)&pWhh, g_Whh);
    cudaGetSymbolAddress((void**)&pWhm, g_Whm);
    cudaGetSymbolAddress((void**)&pWdh, g_Wdh);
    cudaGetSymbolAddress((void**)&pWdm, g_Wdm);
    cudaGetSymbolAddress((void**)&pAE, g_AE);
    cudaGetSymbolAddress((void**)&pBASE, g_BASE);
    cudaGetSymbolAddress((void**)&pENT, g_ENT);

    cudaFuncSetAttribute(gemm_bf<2, 1>, cudaFuncAttributeMaxDynamicSharedMemorySize, GSM_BYTES);
    cudaFuncSetAttribute(gemm_bf<0, 0>, cudaFuncAttributeMaxDynamicSharedMemorySize, GSM_BYTES);

    packW_kernel<<<1408, 256>>>(emb2w, hm1w, decw);
    h1_kernel<<<NA / 2, 256>>>(emb, emb1w, emb1b);
    foldA_kernel<<<8, 256>>>(hew, hm2w, hm2b, qw, kw);
    foldB_kernel<<<13, 256>>>(heb);

    // AE = leaky(H1 @ emb2_w^T + b) -> float g_AE + split FIN[:,0:256]
    gemm_bf<2, 1><<<dim3(4, 32), 256, GSM_BYTES>>>(pH1h, pH1m, 128, pWeh, pWem, 128,
                                                   emb2b, pAE, 256, pFh, pFm, 512, 128);
    // BASE = AE @ hm1_w[:,:256]^T + hm1_b (A = split FIN cols 0-255)
    gemm_bf<0, 0><<<dim3(4, 32), 256, GSM_BYTES>>>(pFh, pFm, 512, pWhh, pWhm, 256,
                                                   hm1b, pBASE, 256, nullptr, nullptr, 0, 256);
    // fused edge pipeline; writes split FIN[:,256:512] + 4 outputs
    edge_kernel<<<NA, 256>>>(emb, gum, hm1w, vw, vb, out);
    // output = FIN @ dec_w^T + dec_b
    gemm_bf<0, 0><<<dim3(8, 32), 256, GSM_BYTES>>>(pFh, pFm, 512, pWdh, pWdm, 512,
                                                   decb, out, 512, nullptr, nullptr, 0, 512);
    ent_reduce<<<1, 256>>>(pENT, out + OFF_ENT);
}

// round 13
// speedup vs baseline: 1.6777x; 1.0126x over previous
#include <cuda_runtime.h>
#include <cuda_bf16.h>
#include <stdint.h>
#include <math.h>

#define BLK 256
#define NAG 32
#define NA  4096
#define DD  256
#define NE  31

#define OFF_LOG 2097152L
#define OFF_UNN 2224128L
#define OFF_ENT 2351104L
#define OFF_HW  2351105L
#define OFF_CMB 2478081L

typedef __nv_bfloat16 bf16;

// ------- scratch: bf16 (hi, mid) planes for all GEMM operands -------
__device__ __align__(16) bf16 g_H1h[NA * 128], g_H1m[NA * 128];
__device__ __align__(16) bf16 g_FINh[NA * 512], g_FINm[NA * 512];   // [AE | X]
__device__ __align__(16) bf16 g_Weh[256 * 128], g_Wem[256 * 128];
__device__ __align__(16) bf16 g_Whh[256 * 256], g_Whm[256 * 256];
__device__ __align__(16) bf16 g_Wdh[512 * 512], g_Wdm[512 * 512];
__device__ float g_AE[NA * DD];
__device__ float g_BASE[NA * DD];
__device__ float g_ENT[NA];
__device__ float g_W2e[2 * DD];
__device__ float g_b2e[2];
__device__ float g_QKW[DD * 10];
__device__ float g_pW2e[8 * 512];
__device__ float g_pQKW[8 * DD * 10];
__device__ float g_pb2e[16];

// ------- bf16 2-way split -------
__device__ __forceinline__ void split2(float x, bf16& h, bf16& m) {
    h = __float2bfloat16_rn(x);
    m = __float2bfloat16_rn(x - __bfloat162float(h));
}

// ------- bf16 m16n8k16 MMA + ldmatrix + cp.async -------
__device__ __forceinline__ void mma_bf16(float* d, const uint32_t* a,
                                         uint32_t b0, uint32_t b1) {
    asm volatile(
        "mma.sync.aligned.m16n8k16.row.col.f32.bf16.bf16.f32 "
        "{%0,%1,%2,%3}, {%4,%5,%6,%7}, {%8,%9}, {%0,%1,%2,%3};\n"
        : "+f"(d[0]), "+f"(d[1]), "+f"(d[2]), "+f"(d[3])
        : "r"(a[0]), "r"(a[1]), "r"(a[2]), "r"(a[3]), "r"(b0), "r"(b1));
}
__device__ __forceinline__ void ldsm4(uint32_t* r, uint32_t p) {
    asm volatile("ldmatrix.sync.aligned.m8n8.x4.shared.b16 {%0,%1,%2,%3}, [%4];"
        : "=r"(r[0]), "=r"(r[1]), "=r"(r[2]), "=r"(r[3]) : "r"(p));
}
__device__ __forceinline__ void ldsm2(uint32_t& r0, uint32_t& r1, uint32_t p) {
    asm volatile("ldmatrix.sync.aligned.m8n8.x2.shared.b16 {%0,%1}, [%2];"
        : "=r"(r0), "=r"(r1) : "r"(p));
}
__device__ __forceinline__ void cpa16(uint32_t s, const void* g) {
    asm volatile("cp.async.cg.shared.global [%0], [%1], 16;" :: "r"(s), "l"(g));
}

// ------- bf16-split tensor GEMM, cp.async double-buffered, ldmatrix ----
// C = act(A[MxK] @ W[NxK]^T + bias).  BM=128, BN=64, BK=32, 256 threads,
// 8 warps 4(m)x2(n), warp tile 32x32.  3 passes: hh + mh + hm.
#define SSTR 20
#define AW   (128 * SSTR)
#define BW   (64 * SSTR)
#define STGW (2 * AW + 2 * BW)
#define GSM_BYTES (2 * STGW * 4)
template <int ACT, int PACK>
__global__ void __launch_bounds__(256)
gemm_bf(const bf16* __restrict__ Ah, const bf16* __restrict__ Am, int lda,
        const bf16* __restrict__ Wh, const bf16* __restrict__ Wm, int ldw,
        const float* __restrict__ bias, float* __restrict__ C, int ldc,
        bf16* __restrict__ Cph, bf16* __restrict__ Cpm, int ldcp, int K)
{
    extern __shared__ uint32_t SM[];
    uint32_t sbase = (uint32_t)__cvta_generic_to_shared(SM);

    int tid = threadIdx.x;
    int lane = tid & 31, wid = tid >> 5;
    int g = lane >> 2, tig = lane & 3;
    int wm = wid >> 1, wn = wid & 1;
    int bm = blockIdx.y * 128, bn = blockIdx.x * 64;

    float acc[2][4][4];
#pragma unroll
    for (int mt = 0; mt < 2; mt++)
#pragma unroll
        for (int nt = 0; nt < 4; nt++)
#pragma unroll
            for (int q = 0; q < 4; q++) acc[mt][nt][q] = 0.f;

    // ldmatrix lane base offsets (bytes)
    uint32_t aoff = (uint32_t)(((wm * 32 + (lane & 15)) * SSTR + (lane >> 4) * 4) * 4);
    uint32_t boff = (uint32_t)((((lane & 7)) * SSTR + ((lane >> 3) & 1) * 4) * 4);

    // staging: A planes 512 chunks each (2 iters/thread), B planes 256 (1 iter)
    int ar0 = tid >> 2, ac0 = tid & 3;
    int ar1 = (tid + 256) >> 2;
    const bf16* pA0h = Ah + (size_t)(bm + ar0) * lda + ac0 * 8;
    const bf16* pA0m = Am + (size_t)(bm + ar0) * lda + ac0 * 8;
    const bf16* pA1h = Ah + (size_t)(bm + ar1) * lda + ac0 * 8;
    const bf16* pA1m = Am + (size_t)(bm + ar1) * lda + ac0 * 8;
    const bf16* pW0h = Wh + (size_t)(bn + ar0) * ldw + ac0 * 8;
    const bf16* pW0m = Wm + (size_t)(bn + ar0) * ldw + ac0 * 8;
    uint32_t o0 = (uint32_t)(ar0 * SSTR + ac0 * 4) * 4;
    uint32_t o1 = (uint32_t)(ar1 * SSTR + ac0 * 4) * 4;

    int nk = K / 32;
#define STAGE(s, k0) do {                                            \
        uint32_t db = sbase + (uint32_t)(s) * STGW * 4;              \
        cpa16(db + o0, pA0h + (k0));                                 \
        cpa16(db + o1, pA1h + (k0));                                 \
        cpa16(db + AW * 4 + o0, pA0m + (k0));                        \
        cpa16(db + AW * 4 + o1, pA1m + (k0));                        \
        cpa16(db + 2 * AW * 4 + o0, pW0h + (k0));                    \
        cpa16(db + (2 * AW + BW) * 4 + o0, pW0m + (k0));             \
    } while (0)

    STAGE(0, 0);
    asm volatile("cp.async.commit_group;");
    if (nk > 1) STAGE(1, 32);
    asm volatile("cp.async.commit_group;");

    for (int t = 0; t < nk; t++) {
        asm volatile("cp.async.wait_group 1;");
        __syncthreads();
        int s = t & 1;
        uint32_t stg = sbase + (uint32_t)s * STGW * 4;
#pragma unroll
        for (int ks = 0; ks < 2; ks++) {
            uint32_t kwb = (uint32_t)(ks * 8 * 4);
            uint32_t ah[2][4], am[2][4];
#pragma unroll
            for (int mt = 0; mt < 2; mt++) {
                uint32_t ap = stg + aoff + (uint32_t)(mt * 16 * SSTR * 4) + kwb;
                ldsm4(ah[mt], ap);
                ldsm4(am[mt], ap + AW * 4);
            }
#pragma unroll
            for (int nt = 0; nt < 4; nt++) {
                uint32_t bp = stg + 2 * AW * 4 + boff
                            + (uint32_t)((wn * 32 + nt * 8) * SSTR * 4) + kwb;
                uint32_t bh0, bh1, bm0, bm1;
                ldsm2(bh0, bh1, bp);
                ldsm2(bm0, bm1, bp + BW * 4);
#pragma unroll
                for (int mt = 0; mt < 2; mt++) {
                    mma_bf16(acc[mt][nt], ah[mt], bh0, bh1);   // hi*hi
                    mma_bf16(acc[mt][nt], am[mt], bh0, bh1);   // mid*hi
                    mma_bf16(acc[mt][nt], ah[mt], bm0, bm1);   // hi*mid
                }
            }
        }
        __syncthreads();
        if (t + 2 < nk) STAGE(s, (t + 2) * 32);
        asm volatile("cp.async.commit_group;");
    }
#undef STAGE

    // epilogue
#pragma unroll
    for (int mt = 0; mt < 2; mt++) {
        long gm0 = bm + wm * 32 + mt * 16 + g;
        long gm1 = gm0 + 8;
#pragma unroll
        for (int nt = 0; nt < 4; nt++) {
            long gn = bn + wn * 32 + nt * 8 + 2 * tig;
            float b0 = bias[gn], b1 = bias[gn + 1];
            float v00 = acc[mt][nt][0] + b0, v01 = acc[mt][nt][1] + b1;
            float v10 = acc[mt][nt][2] + b0, v11 = acc[mt][nt][3] + b1;
            if (ACT == 1) {
                v00 = fmaxf(v00, 0.f); v01 = fmaxf(v01, 0.f);
                v10 = fmaxf(v10, 0.f); v11 = fmaxf(v11, 0.f);
            }
            if (ACT == 2) {
                v00 = v00 > 0.f ? v00 : 0.01f * v00;
                v01 = v01 > 0.f ? v01 : 0.01f * v01;
                v10 = v10 > 0.f ? v10 : 0.01f * v10;
                v11 = v11 > 0.f ? v11 : 0.01f * v11;
            }
            *(float2*)&C[gm0 * ldc + gn] = make_float2(v00, v01);
            *(float2*)&C[gm1 * ldc + gn] = make_float2(v10, v11);
            if (PACK) {
                bf16 h, m;
                split2(v00, h, m); Cph[gm0 * ldcp + gn] = h;     Cpm[gm0 * ldcp + gn] = m;
                split2(v01, h, m); Cph[gm0 * ldcp + gn + 1] = h; Cpm[gm0 * ldcp + gn + 1] = m;
                split2(v10, h, m); Cph[gm1 * ldcp + gn] = h;     Cpm[gm1 * ldcp + gn] = m;
                split2(v11, h, m); Cph[gm1 * ldcp + gn + 1] = h; Cpm[gm1 * ldcp + gn + 1] = m;
            }
        }
    }
}

// ------- merged prep: packW (1408 blk) + h1 (2048 blk) + foldA (8 blk) --
#define PREP_PACKW 1408
#define PREP_H1    2048
#define PREP_FOLDA 8
#define PREP_GRID  (PREP_PACKW + PREP_H1 + PREP_FOLDA)
__global__ void prep_kernel(const float* __restrict__ emb2w,
                            const float* __restrict__ hm1w,
                            const float* __restrict__ decw,
                            const float* __restrict__ emb,
                            const float* __restrict__ emb1w,
                            const float* __restrict__ emb1b,
                            const float* __restrict__ he_w,
                            const float* __restrict__ hm2_w,
                            const float* __restrict__ hm2_b,
                            const float* __restrict__ q_w,
                            const float* __restrict__ k_w)
{
    __shared__ float sw[128 * 5];
    __shared__ float sb2[128];
    int b = blockIdx.x;
    int tid = threadIdx.x;

    if (b < PREP_PACKW) {
        int i = b * 256 + tid;
        bf16 h, m;
        if (i < 32768) {
            split2(emb2w[i], h, m);
            g_Weh[i] = h; g_Wem[i] = m;
        } else if (i < 98304) {
            int j = i - 32768;
            split2(hm1w[(j >> 8) * 263 + (j & 255)], h, m);
            g_Whh[j] = h; g_Whm[j] = m;
        } else if (i < 360448) {
            int j = i - 98304;
            split2(decw[j], h, m);
            g_Wdh[j] = h; g_Wdm[j] = m;
        }
        return;
    }
    if (b < PREP_PACKW + PREP_H1) {
        int hb = b - PREP_PACKW;
        for (int e = tid; e < 640; e += 256) sw[e] = emb1w[e];
        if (tid < 128) sb2[tid] = emb1b[tid];
        __syncthreads();
        int r = hb * 2 + (tid >> 7);
        int c = tid & 127;
        const float* er = emb + (long)r * 11 + 4;
        float e0 = er[0], e1 = er[1], e2 = er[2], e3 = er[3], e4 = er[4];
        const float* wc = &sw[c * 5];
        float v = sb2[c] + e0 * wc[0] + e1 * wc[1] + e2 * wc[2] + e3 * wc[3] + e4 * wc[4];
        v = v > 0.f ? v : 0.01f * v;
        bf16 h, m;
        split2(v, h, m);
        long idx = (long)r * 128 + c;
        g_H1h[idx] = h; g_H1m[idx] = m;
        return;
    }
    // foldA
    int p = b - PREP_PACKW - PREP_H1;
    int t = tid;
    float s0 = 0.f, s1 = 0.f;
#pragma unroll 8
    for (int m = 0; m < 32; m++) {
        int mm = p * 32 + m;
        float w2 = hm2_w[mm * DD + t];
        s0 += he_w[mm] * w2;
        s1 += he_w[DD + mm] * w2;
    }
    g_pW2e[p * 512 + t] = s0;
    g_pW2e[p * 512 + 256 + t] = s1;

    float acc[10];
#pragma unroll
    for (int f = 0; f < 10; f++) acc[f] = 0.f;
#pragma unroll 4
    for (int d = 0; d < 32; d++) {
        int dd = p * 32 + d;
        float qv = q_w[dd * DD + t];
#pragma unroll
        for (int f = 0; f < 10; f++) acc[f] += qv * k_w[dd * 10 + f];
    }
#pragma unroll
    for (int f = 0; f < 10; f++) g_pQKW[(p * DD + t) * 10 + f] = acc[f];

    if (t < 2) {
        float s = 0.f;
        for (int m = 0; m < 32; m++) {
            int mm = p * 32 + m;
            s += he_w[t * DD + mm] * hm2_b[mm];
        }
        g_pb2e[p * 2 + t] = s;
    }
}

// ------- fold stage B: wide combine -------
__global__ void foldB_kernel(const float* __restrict__ he_b)
{
    int idx = blockIdx.x * 256 + threadIdx.x;
    if (idx < 512) {
        float s = 0.f;
#pragma unroll
        for (int p = 0; p < 8; p++) s += g_pW2e[p * 512 + idx];
        g_W2e[idx] = s;
    } else if (idx < 3072) {
        int j = idx - 512;
        float s = 0.f;
#pragma unroll
        for (int p = 0; p < 8; p++) s += g_pQKW[p * 2560 + j];
        g_QKW[j] = s;
    } else if (idx < 3074) {
        int t = idx - 3072;
        float s = he_b[t];
#pragma unroll
        for (int p = 0; p < 8; p++) s += g_pb2e[p * 2 + t];
        g_b2e[t] = s;
    }
}

// ------- fused per-agent edge kernel -------
#define SEP 12
__global__ void edge_kernel(const float* __restrict__ emb,
                            const float* __restrict__ gum,
                            const float* __restrict__ hm1_w,
                            const float* __restrict__ v_w,
                            const float* __restrict__ v_b,
                            float* __restrict__ out)
{
    int a = blockIdx.x;
    int bb = a >> 5, i = a & 31;
    int tid = threadIdx.x;
    int lane = tid & 31, warp = tid >> 5;

    __shared__ float s_emb[NAG * 11];
    __shared__ float s_WE[DD * 7];
    __shared__ float s_W2[2 * DD];
    __shared__ float s_b2[2];
    __shared__ float s_VW[DD * 10];
    __shared__ float s_vb[DD];
    __shared__ float s_base[DD];
    __shared__ float s_qk[10];
    __shared__ __align__(16) float s_se[NAG][SEP];
    __shared__ float s_sc[NAG];
    __shared__ float s_hw[NAG];
    __shared__ float s_cb[NAG];
    __shared__ float s_red[8 * 10];

    for (int e = tid; e < NAG * 11; e += BLK) s_emb[e] = emb[bb * NAG * 11 + e];
    for (int e = tid; e < DD * 7; e += BLK) s_WE[e] = hm1_w[(e / 7) * 263 + 256 + (e % 7)];
    s_W2[tid] = g_W2e[tid];
    s_W2[DD + tid] = g_W2e[DD + tid];
    for (int e = tid; e < DD * 10; e += BLK) s_VW[e] = v_w[e];
    s_vb[tid] = v_b[tid];
    s_base[tid] = g_BASE[(long)a * DD + tid];
    if (tid < 2) s_b2[tid] = g_b2e[tid];

    float av = g_AE[(long)a * DD + tid];
#pragma unroll
    for (int f = 0; f < 10; f++) {
        float p = av * g_QKW[tid * 10 + f];
        for (int o = 16; o; o >>= 1) p += __shfl_down_sync(0xffffffffu, p, o);
        if (lane == 0) s_red[warp * 10 + f] = p;
    }
    __syncthreads();
    if (tid < 10) {
        float s = 0.f;
        for (int w = 0; w < 8; w++) s += s_red[w * 10 + tid];
        s_qk[tid] = s;
    }
    __syncthreads();

    if (tid < NAG) {
        int j = tid;
        s_se[j][10] = 0.f; s_se[j][11] = 0.f;
        if (j == i) {
            s_sc[j] = -1e30f; s_hw[j] = 0.f; s_cb[j] = 0.f;
#pragma unroll
            for (int f = 0; f < 10; f++) s_se[j][f] = 0.f;
        } else {
            const float* ei = &s_emb[i * 11];
            const float* ej = &s_emb[j * 11];
            float dx = ej[0] - ei[0], dy = ej[1] - ei[1];
            float r = sqrtf(dx * dx + dy * dy);
            float hx = ei[2], hy = ei[3];
            float hr = sqrtf(hx * hx + hy * hy);
            float inv = 1.f / (r * hr);
            float se[10];
            se[0] = r * (1.f / 12.f);
            se[1] = (dx * hx + dy * hy) * inv;
            se[2] = (dy * hx - dx * hy) * inv;
            se[3] = ej[2]; se[4] = ej[3];
            se[5] = ej[7]; se[6] = ej[8];
            float gx = ej[9] - ei[0], gy = ej[10] - ei[1];
            float gr = sqrtf(gx * gx + gy * gy);
            float ginv = 1.f / (gr * hr);
            se[7] = gr;
            se[8] = (gx * hx + gy * hy) * ginv;
            se[9] = (gy * hx - gx * hy) * ginv;
            float sc = 0.f;
#pragma unroll
            for (int f = 0; f < 10; f++) { s_se[j][f] = se[f]; sc += s_qk[f] * se[f]; }
            s_sc[j] = sc * 0.0625f;
            int jj = j - (j > i);
            out[OFF_UNN + (long)a * NE + jj] = r;
        }
    }
    __syncthreads();

    {
        int jb = warp * 4;
        float e[4][7];
#pragma unroll
        for (int jj = 0; jj < 4; jj++)
#pragma unroll
            for (int f = 0; f < 7; f++) e[jj][f] = s_se[jb + jj][f];
        float acc0[4] = {0.f, 0.f, 0.f, 0.f}, acc1[4] = {0.f, 0.f, 0.f, 0.f};
#pragma unroll
        for (int t = 0; t < 8; t++) {
            int o = lane + t * 32;
            float base = s_base[o];
            const float* we = &s_WE[o * 7];
            float w0 = we[0], w1 = we[1], w2 = we[2], w3 = we[3],
                  w4 = we[4], w5 = we[5], w6 = we[6];
            float W2a = s_W2[o], W2b = s_W2[DD + o];
#pragma unroll
            for (int jj = 0; jj < 4; jj++) {
                float pre = base + w0 * e[jj][0] + w1 * e[jj][1] + w2 * e[jj][2]
                          + w3 * e[jj][3] + w4 * e[jj][4] + w5 * e[jj][5] + w6 * e[jj][6];
                float rr = fmaxf(pre, 0.f);
                acc0[jj] += W2a * rr;
                acc1[jj] += W2b * rr;
            }
        }
#pragma unroll
        for (int jj = 0; jj < 4; jj++) {
            for (int o = 16; o; o >>= 1) {
                acc0[jj] += __shfl_down_sync(0xffffffffu, acc0[jj], o);
                acc1[jj] += __shfl_down_sync(0xffffffffu, acc1[jj], o);
            }
        }
        if (lane == 0) {
#pragma unroll
            for (int jj = 0; jj < 4; jj++) {
                int j = jb + jj;
                if (j == i) continue;
                float l0 = acc0[jj] + s_b2[0], l1 = acc1[jj] + s_b2[1];
                int jx = j - (j > i);
                long gidx = ((long)a * NE + jx) * 2;
                float u0 = gum[gidx], u1 = gum[gidx + 1];
                float g0 = -logf(-logf(u0 + 1e-10f) + 1e-10f);
                float g1 = -logf(-logf(u1 + 1e-10f) + 1e-10f);
                float z0 = (l0 + g0) * 2.f, z1 = (l1 + g1) * 2.f;
                float zm = fmaxf(z0, z1);
                float x0 = expf(z0 - zm), x1 = expf(z1 - zm);
                float p1 = x1 / (x0 + x1);
                s_hw[j] = p1;
                out[OFF_LOG + (long)a * NE + jx] = l1;
                out[OFF_HW + (long)a * NE + jx] = p1;
            }
        }
    }
    __syncthreads();

    if (tid < NAG) {
        float sc = s_sc[tid];
        float m = sc;
        for (int o = 16; o; o >>= 1) m = fmaxf(m, __shfl_xor_sync(0xffffffffu, m, o));
        float ev = (tid == i) ? 0.f : expf(sc - m);
        float sum = ev;
        for (int o = 16; o; o >>= 1) sum += __shfl_xor_sync(0xffffffffu, sum, o);
        float sw = ev / sum;
        float cb = sw * s_hw[tid];
        s_cb[tid] = cb;
        float csum = cb;
        for (int o = 16; o; o >>= 1) csum += __shfl_xor_sync(0xffffffffu, csum, o);
        float cwn = cb / (csum + 1e-6f);
        float ent = (tid == i) ? 0.f : (-cwn * logf(cwn + 1e-6f));
        for (int o = 16; o; o >>= 1) ent += __shfl_xor_sync(0xffffffffu, ent, o);
        if (tid == 0) g_ENT[a] = ent;
        if (tid != i) out[OFF_CMB + (long)a * NE + (tid - (tid > i))] = cb;
    }
    __syncthreads();

    {
        int o = tid;
        float vb = s_vb[o];
        float vw[10];
#pragma unroll
        for (int f = 0; f < 10; f++) vw[f] = s_VW[o * 10 + f];
        float acc = 0.f;
#pragma unroll 4
        for (int j = 0; j < NAG; j++) {
            float c = s_cb[j];
            float4 p0 = *(const float4*)&s_se[j][0];
            float4 p1 = *(const float4*)&s_se[j][4];
            float4 p2 = *(const float4*)&s_se[j][8];
            float vv = vb;
            vv += vw[0] * p0.x + vw[1] * p0.y + vw[2] * p0.z + vw[3] * p0.w;
            vv += vw[4] * p1.x + vw[5] * p1.y + vw[6] * p1.z + vw[7] * p1.w;
            vv += vw[8] * p2.x + vw[9] * p2.y;
            acc += c * fmaxf(vv, 0.f);
        }
        bf16 h, m;
        split2(acc, h, m);
        long idx = (long)a * 512 + 256 + o;
        g_FINh[idx] = h; g_FINm[idx] = m;
    }
}

// ------- deterministic entropy reduction -------
__global__ void ent_reduce(const float* __restrict__ ent, float* __restrict__ out)
{
    __shared__ float s[256];
    float v = 0.f;
    for (int k = threadIdx.x; k < NA; k += 256) v += ent[k];
    s[threadIdx.x] = v;
    __syncthreads();
    for (int o = 128; o; o >>= 1) {
        if (threadIdx.x < o) s[threadIdx.x] += s[threadIdx.x + o];
        __syncthreads();
    }
    if (threadIdx.x == 0) out[0] = s[0] * (1.f / 4096.f);
}

extern "C" void kernel_launch(void* const* d_in, const int* in_sizes, int n_in,
                              void* d_out, int out_size)
{
    const float* emb   = (const float*)d_in[0];
    const float* gum   = (const float*)d_in[1];
    const float* emb1w = (const float*)d_in[2];
    const float* emb1b = (const float*)d_in[3];
    const float* emb2w = (const float*)d_in[4];
    const float* emb2b = (const float*)d_in[5];
    const float* hm1w  = (const float*)d_in[6];
    const float* hm1b  = (const float*)d_in[7];
    const float* hm2w  = (const float*)d_in[8];
    const float* hm2b  = (const float*)d_in[9];
    const float* hew   = (const float*)d_in[10];
    const float* heb   = (const float*)d_in[11];
    const float* qw    = (const float*)d_in[12];
    const float* kw    = (const float*)d_in[13];
    const float* vw    = (const float*)d_in[14];
    const float* vb    = (const float*)d_in[15];
    const float* decw  = (const float*)d_in[16];
    const float* decb  = (const float*)d_in[17];
    float* out = (float*)d_out;

    bf16 *pH1h, *pH1m, *pFh, *pFm;
    bf16 *pWeh, *pWem, *pWhh, *pWhm, *pWdh, *pWdm;
    float *pAE, *pBASE, *pENT;
    cudaGetSymbolAddress((void**)&pH1h, g_H1h);
    cudaGetSymbolAddress((void**)&pH1m, g_H1m);
    cudaGetSymbolAddress((void**)&pFh, g_FINh);
    cudaGetSymbolAddress((void**)&pFm, g_FINm);
    cudaGetSymbolAddress((void**)&pWeh, g_Weh);
    cudaGetSymbolAddress((void**)&pWem, g_Wem);
    cudaGetSymbolAddress((void**)&pWhh, g_Whh);
    cudaGetSymbolAddress((void**)&pWhm, g_Whm);
    cudaGetSymbolAddress((void**)&pWdh, g_Wdh);
    cudaGetSymbolAddress((void**)&pWdm, g_Wdm);
    cudaGetSymbolAddress((void**)&pAE, g_AE);
    cudaGetSymbolAddress((void**)&pBASE, g_BASE);
    cudaGetSymbolAddress((void**)&pENT, g_ENT);

    cudaFuncSetAttribute(gemm_bf<2, 1>, cudaFuncAttributeMaxDynamicSharedMemorySize, GSM_BYTES);
    cudaFuncSetAttribute(gemm_bf<0, 0>, cudaFuncAttributeMaxDynamicSharedMemorySize, GSM_BYTES);

    prep_kernel<<<PREP_GRID, 256>>>(emb2w, hm1w, decw, emb, emb1w, emb1b,
                                    hew, hm2w, hm2b, qw, kw);
    foldB_kernel<<<13, 256>>>(heb);

    // AE = leaky(H1 @ emb2_w^T + b) -> float g_AE + split FIN[:,0:256]
    gemm_bf<2, 1><<<dim3(4, 32), 256, GSM_BYTES>>>(pH1h, pH1m, 128, pWeh, pWem, 128,
                                                   emb2b, pAE, 256, pFh, pFm, 512, 128);
    // BASE = AE @ hm1_w[:,:256]^T + hm1_b (A = split FIN cols 0-255)
    gemm_bf<0, 0><<<dim3(4, 32), 256, GSM_BYTES>>>(pFh, pFm, 512, pWhh, pWhm, 256,
                                                   hm1b, pBASE, 256, nullptr, nullptr, 0, 256);
    // fused edge pipeline; writes split FIN[:,256:512] + 4 outputs
    edge_kernel<<<NA, 256>>>(emb, gum, hm1w, vw, vb, out);
    // output = FIN @ dec_w^T + dec_b
    gemm_bf<0, 0><<<dim3(8, 32), 256, GSM_BYTES>>>(pFh, pFm, 512, pWdh, pWdm, 512,
                                                   decb, out, 512, nullptr, nullptr, 0, 512);
    ent_reduce<<<1, 256>>>(pENT, out + OFF_ENT);
}